// round 12
// baseline (speedup 1.0000x reference)
#include <cuda_runtime.h>
#include <math.h>
#include <stdint.h>
#include <stddef.h>

#define CCH 160
#define NT  110592          // 48*48*48
#define HWS 2304
#define WS  48
#define BN  192
#define NTILES_N (NT / BN)  // 576 n-tiles; x2 m-halves = 1152 work items
#define GRID_P 296          // persistent CTAs (2 per SM, paired by m-half)
#define NTHR 192            // 6 warps: 1(M) x 6(N)

#define WH_F4   3200                 // W half: 80 rows x 160 k = 12800 floats = 3200 float4
#define STAGE_F (BN * 36)            // 6912 floats per stage
#define S0      200                  // mode-0 [k][n] stage stride (192 + 8)
#define NSTAGE  2
#define SMEM_BYTES (WH_F4 * 16 + NSTAGE * STAGE_F * 4)   // 51200 + 55296 = 106496

// ---------------- device globals (scratch; no allocation allowed) -------------
__device__ __align__(16) float g_h [(size_t)NT * CCH];   // h0 then h1 in place, [n][c]
__device__ __align__(16) float g_y [(size_t)NT * CCH];   // branch sum, [n][c]
__device__ __align__(16) float g_Wf[5 * CCH * CCH];      // half-major fragment weights
__device__ float  g_b3f[CCH];                            // folded bias for final GEMM
__device__ double g_stats[4];

// ---------------- helpers ----------------
__device__ __forceinline__ float gelu_erf(float t) {
    return 0.5f * t * (1.0f + erff(t * 0.70710678118654752f));
}
__device__ __forceinline__ float rna_tf32(float x) {
    float r; asm("cvt.rna.tf32.f32 %0, %1;" : "=f"(r) : "f"(x)); return r;
}
__device__ __forceinline__ void mma8(float* c, uint4 a, uint32_t b0, uint32_t b1) {
    asm("mma.sync.aligned.m16n8k8.row.col.f32.tf32.tf32.f32 "
        "{%0,%1,%2,%3}, {%4,%5,%6,%7}, {%8,%9}, {%0,%1,%2,%3};"
        : "+f"(c[0]), "+f"(c[1]), "+f"(c[2]), "+f"(c[3])
        : "r"(a.x), "r"(a.y), "r"(a.z), "r"(a.w), "r"(b0), "r"(b1));
}
__device__ __forceinline__ uint32_t smem_u32(const void* p) {
    uint32_t a;
    asm("{ .reg .u64 t; cvta.to.shared.u64 t, %1; cvt.u32.u64 %0, t; }" : "=r"(a) : "l"(p));
    return a;
}
__device__ __forceinline__ void cpa16(uint32_t dst, const void* src, int sz) {
    asm volatile("cp.async.ca.shared.global [%0], [%1], 16, %2;"
                 :: "r"(dst), "l"(src), "r"(sz) : "memory");
}
#define CPA_COMMIT() asm volatile("cp.async.commit_group;" ::: "memory")
#define CPA_WAIT1()  asm volatile("cp.async.wait_group 1;" ::: "memory")

// ---------------- prep: fragment-order + tf32-round weights; zero stats ------
// per gid: [mhalf(2)][mt(5)][kstep(20)][lane(32)] float4; m0 = mhalf*80+mt*16+g
__global__ void prep_w(const float* __restrict__ w1, const float* __restrict__ w21,
                       const float* __restrict__ w22, const float* __restrict__ w23) {
    if (blockIdx.x == 0 && blockIdx.y == 0 && threadIdx.x < 4)
        g_stats[threadIdx.x] = 0.0;
    const int gid = blockIdx.y;
    const float* W = (gid == 0) ? w1 : (gid == 1) ? w21 : (gid == 2) ? w22 : w23;
    int idx = blockIdx.x * 256 + threadIdx.x;       // < 6400
    if (idx >= 6400) return;
    int mhalf = idx / 3200;
    int rem   = idx % 3200;
    int mt    = rem / 640;
    int r2    = rem % 640;
    int kstep = r2 / 32;
    int lane  = r2 % 32;
    int g = lane >> 2, tig = lane & 3;
    int m0 = mhalf * 80 + mt * 16 + g;
    int k0 = kstep * 8 + tig;
    float4 o;
    o.x = rna_tf32(W[m0 * CCH + k0]);
    o.y = rna_tf32(W[(m0 + 8) * CCH + k0]);
    o.z = rna_tf32(W[m0 * CCH + k0 + 4]);
    o.w = rna_tf32(W[(m0 + 8) * CCH + k0 + 4]);
    reinterpret_cast<float4*>(g_Wf)[(size_t)gid * 6400 + idx] = o;
}

// ---------------- gelu pass with GN1 finalize fused --------------------------
__global__ void gelu_fin(const float* __restrict__ g1, const float* __restrict__ be1) {
    __shared__ double sMu, sRs;
    __shared__ float sA[CCH], sB[CCH];
    const int t = threadIdx.x;
    if (t == 0) {
        double Nd = (double)CCH * (double)NT;
        double m  = g_stats[0] / Nd;
        double v  = g_stats[1] / Nd - m * m;
        sMu = m; sRs = 1.0 / sqrt(v + 1e-5);
    }
    __syncthreads();
    if (t < CCH) {
        double mu = sMu, rs = sRs;
        sA[t] = (float)((double)g1[t] * rs);
        sB[t] = (float)((double)be1[t] - mu * (double)g1[t] * rs);
    }
    __syncthreads();
    size_t i4 = (size_t)blockIdx.x * blockDim.x + t;
    if (i4 >= (size_t)NT * CCH / 4) return;
    const int c0 = (int)((i4 * 4) % CCH);
    float4 v = reinterpret_cast<float4*>(g_h)[i4];
    v.x = rna_tf32(gelu_erf(fmaf(sA[c0 + 0], v.x, sB[c0 + 0])));
    v.y = rna_tf32(gelu_erf(fmaf(sA[c0 + 1], v.y, sB[c0 + 1])));
    v.z = rna_tf32(gelu_erf(fmaf(sA[c0 + 2], v.z, sB[c0 + 2])));
    v.w = rna_tf32(gelu_erf(fmaf(sA[c0 + 3], v.w, sB[c0 + 3])));
    reinterpret_cast<float4*>(g_h)[i4] = v;
}

// ---------------- GN2 finalize + w3/b3 fold, one kernel ----------------------
__global__ void final_prep(const float* __restrict__ w3, const float* __restrict__ b3,
                           const float* __restrict__ g2, const float* __restrict__ be2) {
    __shared__ double sMu, sRs;
    __shared__ float sA[CCH], sB[CCH];
    const int t = threadIdx.x;
    if (t == 0) {
        double Nd = (double)CCH * (double)NT;
        double m  = g_stats[2] / Nd;
        double v  = g_stats[3] / Nd - m * m;
        sMu = m; sRs = 1.0 / sqrt(v + 1e-5);
    }
    __syncthreads();
    if (t < CCH) {
        double mu = sMu, rs = sRs;
        sA[t] = (float)((double)g2[t] * rs);
        sB[t] = (float)((double)be2[t] - mu * (double)g2[t] * rs);
    }
    __syncthreads();
    if (blockIdx.x < 25) {
        int idx = blockIdx.x * 256 + t;             // < 6400
        int mhalf = idx / 3200;
        int rem   = idx % 3200;
        int mt    = rem / 640;
        int r2    = rem % 640;
        int kstep = r2 / 32;
        int lane  = r2 % 32;
        int g = lane >> 2, tig = lane & 3;
        int m0 = mhalf * 80 + mt * 16 + g;
        int k0 = kstep * 8 + tig;
        float4 o;
        o.x = rna_tf32(w3[m0 * CCH + k0]       * sA[k0]);
        o.y = rna_tf32(w3[(m0 + 8) * CCH + k0] * sA[k0]);
        o.z = rna_tf32(w3[m0 * CCH + k0 + 4]       * sA[k0 + 4]);
        o.w = rna_tf32(w3[(m0 + 8) * CCH + k0 + 4] * sA[k0 + 4]);
        reinterpret_cast<float4*>(g_Wf)[(size_t)4 * 6400 + idx] = o;
    } else if (t < CCH) {
        float s = b3[t];
        for (int k = 0; k < CCH; ++k) s += w3[t * CCH + k] * sB[k];
        g_b3f[t] = s;
    }
}

__device__ __forceinline__ void stats_reduce(float lsum, float lsq, double* dst) {
    double s = (double)lsum, q = (double)lsq;
    #pragma unroll
    for (int o = 16; o > 0; o >>= 1) {
        s += __shfl_down_sync(0xffffffffu, s, o);
        q += __shfl_down_sync(0xffffffffu, q, o);
    }
    __shared__ double red[12];
    const int w = threadIdx.x >> 5, l = threadIdx.x & 31;
    if (l == 0) { red[w] = s; red[6 + w] = q; }
    __syncthreads();
    if (threadIdx.x == 0) {
        double S = 0.0, Q = 0.0;
        #pragma unroll
        for (int i = 0; i < 6; ++i) { S += red[i]; Q += red[6 + i]; }
        atomicAdd(&dst[0], S);
        atomicAdd(&dst[1], Q);
    }
}

// ---------------- M-split persistent tf32 mma GEMM (192thr x 2 CTA/SM) -------
// Each CTA owns m-half (bid&1): W half resident (50 KB). BN=192, nt=4, mt=5.
// MODE 0 : h0 = W1@x  + b1   (B = x direct, [k][n] stage)  -> g_h, GN1 stats
// MODE 10: y  = gelu(W21@sh_d(h1) + b21)    -> g_y store
// MODE 11: y += gelu(W22@sh_h(h1) + b22)    -> g_y RMW
// MODE 12: y += gelu(W23@sh_w(h1) + b23)    -> g_y RMW (rna), GN2 stats
// MODE 2 : out = W3'@y + b3'                -> Outp [c][n]
template<int MODE>
__global__ void __launch_bounds__(NTHR, 2) gemm_mma(
    int gid, const float* __restrict__ Xp,
    const float* __restrict__ bias, float* __restrict__ Outp)
{
    extern __shared__ __align__(16) float smem[];
    float* Ws = smem;                                  // 12800 floats
    const uint32_t ws_u = smem_u32(smem);
    const uint32_t bs_u = ws_u + WH_F4 * 16;

    const int t = threadIdx.x;
    const int lane = t & 31, wid = t >> 5;             // wid = warp_n (0..5)
    const int g = lane >> 2, tig = lane & 3;
    const int bid = blockIdx.x;
    const int mhalf = bid & 1;
    const int tidx0 = bid >> 1;                        // first n-tile index

    // W half fill (async, first group)
    {
        const float4* wsrc = reinterpret_cast<const float4*>(g_Wf)
                           + (size_t)gid * 6400 + (size_t)mhalf * WH_F4;
        #pragma unroll
        for (int i = 0; i < 17; ++i) {
            const int e = t + i * NTHR;
            if (e < WH_F4)
                cpa16(ws_u + (uint32_t)e * 16, wsrc + e, 16);
        }
        CPA_COMMIT();
    }

    const int ntile = (NTILES_N - tidx0 + 147) / 148;
    const int nq = ntile * 5;
    const float* Bsrc = (MODE == 0) ? Xp : ((MODE == 2) ? g_y : g_h);

    const int r0 = t >> 3;        // [n][c] fill: rows r0 + i*24  (i<8)
    const int fj = t & 7;         // 16B chunk within 32-ch row

    // shift modes: per-tile hoisted state
    const int stride = (MODE == 10) ? HWS : ((MODE == 11) ? WS : 1);
    const ptrdiff_t kdelta = (ptrdiff_t)32 - (ptrdiff_t)stride * CCH;
    const float* sb[8];
    int si[8];

    auto fill = [&](int q) {
        if (q >= nq) return;
        const int tl = q / 5, kc = q % 5;
        const int tileN = (tidx0 + tl * 148) * BN;
        const uint32_t dbase = bs_u + (uint32_t)(q & 1) * (STAGE_F * 4);
        if (MODE == 0) {
            #pragma unroll
            for (int i = 0; i < 8; ++i) {
                const int e = t + i * NTHR;           // 0..1535
                const int k = e / 48, c4 = e % 48;
                cpa16(dbase + (uint32_t)(k * S0 + c4 * 4) * 4,
                      Bsrc + (size_t)(kc * 32 + k) * NT + tileN + c4 * 4, 16);
            }
        } else if (MODE == 2) {
            #pragma unroll
            for (int i = 0; i < 8; ++i) {
                const int r = r0 + i * 24;
                cpa16(dbase + (uint32_t)(r * 36 + fj * 4) * 4,
                      Bsrc + (size_t)(tileN + r) * CCH + kc * 32 + fj * 4, 16);
            }
        } else {
            if (kc == 0) {
                #pragma unroll
                for (int i = 0; i < 8; ++i) {
                    const int n = tileN + r0 + i * 24;
                    si[i] = (MODE == 10) ? (n / HWS)
                          : (MODE == 11) ? ((n / WS) % WS) : (n % WS);
                    sb[i] = Bsrc + (size_t)(n + 2 * stride) * CCH + fj * 4;
                }
            }
            const ptrdiff_t koff = (ptrdiff_t)kc * kdelta;
            #pragma unroll
            for (int i = 0; i < 8; ++i) {
                const int r = r0 + i * 24;
                const int sz = ((unsigned)(si[i] + 2 - kc) < (unsigned)WS) ? 16 : 0;
                cpa16(dbase + (uint32_t)(r * 36 + fj * 4) * 4, sb[i] + koff, sz);
            }
        }
    };

    fill(0); CPA_COMMIT();
    fill(1); CPA_COMMIT();

    float acc[5][4][4];
    #pragma unroll
    for (int mt = 0; mt < 5; ++mt)
        #pragma unroll
        for (int nt = 0; nt < 4; ++nt)
            #pragma unroll
            for (int j = 0; j < 4; ++j) acc[mt][nt][j] = 0.f;
    float lsum = 0.f, lsq = 0.f;

    #pragma unroll 1
    for (int q = 0; q < nq; ++q) {
        CPA_WAIT1();
        __syncthreads();
        const int kc = q % 5;
        const float* Bb = smem + WH_F4 * 4 + (q & 1) * STAGE_F;

        #pragma unroll
        for (int ksl = 0; ksl < 4; ++ksl) {
            const int ks = kc * 4 + ksl;
            uint4 af[5];
            #pragma unroll
            for (int mt = 0; mt < 5; ++mt)
                af[mt] = *reinterpret_cast<const uint4*>(
                    &Ws[((mt * 20 + ks) * 32 + lane) * 4]);
            #pragma unroll
            for (int nt = 0; nt < 4; ++nt) {
                const int nn = wid * 32 + nt * 8 + g;
                uint32_t b0, b1;
                if (MODE == 0) {
                    b0 = __float_as_uint(Bb[(ksl * 8 + tig) * S0 + nn]);
                    b1 = __float_as_uint(Bb[(ksl * 8 + tig + 4) * S0 + nn]);
                } else {
                    b0 = __float_as_uint(Bb[nn * 36 + ksl * 8 + tig]);
                    b1 = __float_as_uint(Bb[nn * 36 + ksl * 8 + tig + 4]);
                }
                #pragma unroll
                for (int mt = 0; mt < 5; ++mt)
                    mma8(acc[mt][nt], af[mt], b0, b1);
            }
        }

        if (kc == 4) {
            // ---- tile epilogue ----
            const int tileN = (tidx0 + (q / 5) * 148) * BN;
            if (MODE != 2) {
                #pragma unroll
                for (int mt = 0; mt < 5; ++mt) {
                    const int m0 = mhalf * 80 + mt * 16 + g;
                    const float bb0 = bias[m0], bb1 = bias[m0 + 8];
                    #pragma unroll
                    for (int nt = 0; nt < 4; ++nt) {
                        const int n0 = tileN + wid * 32 + nt * 8 + tig * 2;
                        float v[4];
                        v[0] = acc[mt][nt][0] + bb0;
                        v[1] = acc[mt][nt][1] + bb0;
                        v[2] = acc[mt][nt][2] + bb1;
                        v[3] = acc[mt][nt][3] + bb1;
                        const size_t a00 = (size_t)n0 * CCH + m0;
                        const size_t a01 = (size_t)(n0 + 1) * CCH + m0;
                        if (MODE == 0) {
                            #pragma unroll
                            for (int j = 0; j < 4; ++j) { lsum += v[j]; lsq += v[j] * v[j]; }
                            g_h[a00] = v[0]; g_h[a01] = v[1];
                            g_h[a00 + 8] = v[2]; g_h[a01 + 8] = v[3];
                        } else {
                            #pragma unroll
                            for (int j = 0; j < 4; ++j) v[j] = gelu_erf(v[j]);
                            if (MODE != 10) {
                                v[0] += g_y[a00]; v[1] += g_y[a01];
                                v[2] += g_y[a00 + 8]; v[3] += g_y[a01 + 8];
                            }
                            if (MODE == 12) {
                                #pragma unroll
                                for (int j = 0; j < 4; ++j) {
                                    lsum += v[j]; lsq += v[j] * v[j];
                                    v[j] = rna_tf32(v[j]);
                                }
                            }
                            g_y[a00] = v[0]; g_y[a01] = v[1];
                            g_y[a00 + 8] = v[2]; g_y[a01 + 8] = v[3];
                        }
                    }
                }
            } else {
                #pragma unroll
                for (int mt = 0; mt < 5; ++mt) {
                    const int m0 = mhalf * 80 + mt * 16 + g;
                    const float bb0 = g_b3f[m0], bb1 = g_b3f[m0 + 8];
                    #pragma unroll
                    for (int nt = 0; nt < 4; ++nt) {
                        const int n0 = tileN + wid * 32 + nt * 8 + tig * 2;
                        float2 o0 = {acc[mt][nt][0] + bb0, acc[mt][nt][1] + bb0};
                        float2 o1 = {acc[mt][nt][2] + bb1, acc[mt][nt][3] + bb1};
                        *reinterpret_cast<float2*>(Outp + (size_t)m0 * NT + n0)       = o0;
                        *reinterpret_cast<float2*>(Outp + (size_t)(m0 + 8) * NT + n0) = o1;
                    }
                }
            }
            #pragma unroll
            for (int mt = 0; mt < 5; ++mt)
                #pragma unroll
                for (int nt = 0; nt < 4; ++nt)
                    #pragma unroll
                    for (int j = 0; j < 4; ++j) acc[mt][nt][j] = 0.f;
        }

        __syncthreads();            // all warps done reading stage q&1
        fill(q + 2);                // refill it
        CPA_COMMIT();
    }

    if (MODE == 0)  stats_reduce(lsum, lsq, &g_stats[0]);
    if (MODE == 12) stats_reduce(lsum, lsq, &g_stats[2]);
}

// ---------------- launcher ----------------
extern "C" void kernel_launch(void* const* d_in, const int* in_sizes, int n_in,
                              void* d_out, int out_size) {
    const float* x   = (const float*)d_in[0];
    const float* w1  = (const float*)d_in[1];
    const float* b1  = (const float*)d_in[2];
    const float* g1  = (const float*)d_in[3];
    const float* be1 = (const float*)d_in[4];
    const float* w21 = (const float*)d_in[5];
    const float* b21 = (const float*)d_in[6];
    const float* w22 = (const float*)d_in[7];
    const float* b22 = (const float*)d_in[8];
    const float* w23 = (const float*)d_in[9];
    const float* b23 = (const float*)d_in[10];
    const float* g2  = (const float*)d_in[11];
    const float* be2 = (const float*)d_in[12];
    const float* w3  = (const float*)d_in[13];
    const float* b3  = (const float*)d_in[14];
    float* out = (float*)d_out;

    cudaFuncSetAttribute(gemm_mma<0>,  cudaFuncAttributeMaxDynamicSharedMemorySize, SMEM_BYTES);
    cudaFuncSetAttribute(gemm_mma<10>, cudaFuncAttributeMaxDynamicSharedMemorySize, SMEM_BYTES);
    cudaFuncSetAttribute(gemm_mma<11>, cudaFuncAttributeMaxDynamicSharedMemorySize, SMEM_BYTES);
    cudaFuncSetAttribute(gemm_mma<12>, cudaFuncAttributeMaxDynamicSharedMemorySize, SMEM_BYTES);
    cudaFuncSetAttribute(gemm_mma<2>,  cudaFuncAttributeMaxDynamicSharedMemorySize, SMEM_BYTES);

    prep_w<<<dim3(25, 4), 256>>>(w1, w21, w22, w23);

    gemm_mma<0><<<GRID_P, NTHR, SMEM_BYTES>>>(0, x, b1, nullptr);
    gelu_fin<<<(int)(((size_t)NT * CCH / 4) / 256), 256>>>(g1, be1);

    gemm_mma<10><<<GRID_P, NTHR, SMEM_BYTES>>>(1, nullptr, b21, nullptr);
    gemm_mma<11><<<GRID_P, NTHR, SMEM_BYTES>>>(2, nullptr, b22, nullptr);
    gemm_mma<12><<<GRID_P, NTHR, SMEM_BYTES>>>(3, nullptr, b23, nullptr);
    final_prep<<<26, 256>>>(w3, b3, g2, be2);

    gemm_mma<2><<<GRID_P, NTHR, SMEM_BYTES>>>(4, nullptr, b3, out);
}

// round 13
// speedup vs baseline: 1.0887x; 1.0887x over previous
#include <cuda_runtime.h>
#include <math.h>
#include <stdint.h>
#include <stddef.h>

#define CCH 160
#define NT  110592          // 48*48*48
#define HWS 2304
#define WS  48
#define BN  192
#define NTILES (NT / BN)    // 576
#define GRID_P 148
#define NTHR 384

#define W_FLOATS  (CCH * CCH)        // 25600
#define STAGE_F   (BN * 36)          // 6912 floats per stage
#define S0        200                // mode-0 [k][n] stage stride
#define SMEM_FLOATS (W_FLOATS + 4 * STAGE_F)        // 53248
#define SMEM_BYTES  (SMEM_FLOATS * 4)               // 212992

// fused branch kernel
#define FB_GRID 296                  // (n-tile, m-half) work items
#define FB_WHALF_F 12800             // 80 rows x 160 k
#define FB_W_F   (3 * FB_WHALF_F)    // 38400 floats = 150 KB
#define FB_SMEM  ((FB_W_F + 2 * STAGE_F) * 4)       // 208896

// ---------------- device globals (scratch; no allocation allowed) -------------
__device__ __align__(16) float g_h [(size_t)NT * CCH];   // h0 then h1 in place, [n][c]
__device__ __align__(16) float g_y [(size_t)NT * CCH];   // branch sum, [n][c]
__device__ __align__(16) float g_Wf[5 * W_FLOATS];       // fragment-ordered weights
__device__ float  g_b3f[CCH];
__device__ double g_stats[4];

// ---------------- helpers ----------------
__device__ __forceinline__ float gelu_erf(float t) {
    return 0.5f * t * (1.0f + erff(t * 0.70710678118654752f));
}
__device__ __forceinline__ float rna_tf32(float x) {
    float r; asm("cvt.rna.tf32.f32 %0, %1;" : "=f"(r) : "f"(x)); return r;
}
__device__ __forceinline__ void mma8(float* c, uint4 a, uint32_t b0, uint32_t b1) {
    asm("mma.sync.aligned.m16n8k8.row.col.f32.tf32.tf32.f32 "
        "{%0,%1,%2,%3}, {%4,%5,%6,%7}, {%8,%9}, {%0,%1,%2,%3};"
        : "+f"(c[0]), "+f"(c[1]), "+f"(c[2]), "+f"(c[3])
        : "r"(a.x), "r"(a.y), "r"(a.z), "r"(a.w), "r"(b0), "r"(b1));
}
__device__ __forceinline__ uint32_t smem_u32(const void* p) {
    uint32_t a;
    asm("{ .reg .u64 t; cvta.to.shared.u64 t, %1; cvt.u32.u64 %0, t; }" : "=r"(a) : "l"(p));
    return a;
}
__device__ __forceinline__ void cpa16(uint32_t dst, const void* src, int sz) {
    asm volatile("cp.async.ca.shared.global [%0], [%1], 16, %2;"
                 :: "r"(dst), "l"(src), "r"(sz) : "memory");
}
#define CPA_COMMIT() asm volatile("cp.async.commit_group;" ::: "memory")
#define CPA_WAIT2()  asm volatile("cp.async.wait_group 2;" ::: "memory")
#define CPA_WAIT1()  asm volatile("cp.async.wait_group 1;" ::: "memory")

// ---------------- prep: fragment-order + tf32-round weights; zero stats ------
// per gid: [mtile(10)][kstep(20)][lane(32)] float4; mtile = mhalf*5+mt
__global__ void prep_w(const float* __restrict__ w1, const float* __restrict__ w21,
                       const float* __restrict__ w22, const float* __restrict__ w23) {
    if (blockIdx.x == 0 && blockIdx.y == 0 && threadIdx.x < 4)
        g_stats[threadIdx.x] = 0.0;
    const int gid = blockIdx.y;
    const float* W = (gid == 0) ? w1 : (gid == 1) ? w21 : (gid == 2) ? w22 : w23;
    int idx = blockIdx.x * 256 + threadIdx.x;       // < 6400
    if (idx >= 6400) return;
    int mtile = idx / 640;
    int rem   = idx % 640;
    int kstep = rem / 32;
    int lane  = rem % 32;
    int g = lane >> 2, tig = lane & 3;
    int m0 = mtile * 16 + g;
    int k0 = kstep * 8 + tig;
    float4 o;
    o.x = rna_tf32(W[m0 * CCH + k0]);
    o.y = rna_tf32(W[(m0 + 8) * CCH + k0]);
    o.z = rna_tf32(W[m0 * CCH + k0 + 4]);
    o.w = rna_tf32(W[(m0 + 8) * CCH + k0 + 4]);
    reinterpret_cast<float4*>(g_Wf)[(size_t)gid * 6400 + idx] = o;
}

// ---------------- gelu pass with GN1 finalize fused --------------------------
__global__ void gelu_fin(const float* __restrict__ g1, const float* __restrict__ be1) {
    __shared__ double sMu, sRs;
    __shared__ float sA[CCH], sB[CCH];
    const int t = threadIdx.x;
    if (t == 0) {
        double Nd = (double)CCH * (double)NT;
        double m  = g_stats[0] / Nd;
        double v  = g_stats[1] / Nd - m * m;
        sMu = m; sRs = 1.0 / sqrt(v + 1e-5);
    }
    __syncthreads();
    if (t < CCH) {
        double mu = sMu, rs = sRs;
        sA[t] = (float)((double)g1[t] * rs);
        sB[t] = (float)((double)be1[t] - mu * (double)g1[t] * rs);
    }
    __syncthreads();
    size_t i4 = (size_t)blockIdx.x * blockDim.x + t;
    if (i4 >= (size_t)NT * CCH / 4) return;
    const int c0 = (int)((i4 * 4) % CCH);
    float4 v = reinterpret_cast<float4*>(g_h)[i4];
    v.x = rna_tf32(gelu_erf(fmaf(sA[c0 + 0], v.x, sB[c0 + 0])));
    v.y = rna_tf32(gelu_erf(fmaf(sA[c0 + 1], v.y, sB[c0 + 1])));
    v.z = rna_tf32(gelu_erf(fmaf(sA[c0 + 2], v.z, sB[c0 + 2])));
    v.w = rna_tf32(gelu_erf(fmaf(sA[c0 + 3], v.w, sB[c0 + 3])));
    reinterpret_cast<float4*>(g_h)[i4] = v;
}

// ---------------- GN2 finalize + w3/b3 fold ----------------------------------
__global__ void final_prep(const float* __restrict__ w3, const float* __restrict__ b3,
                           const float* __restrict__ g2, const float* __restrict__ be2) {
    __shared__ double sMu, sRs;
    __shared__ float sA[CCH], sB[CCH];
    const int t = threadIdx.x;
    if (t == 0) {
        double Nd = (double)CCH * (double)NT;
        double m  = g_stats[2] / Nd;
        double v  = g_stats[3] / Nd - m * m;
        sMu = m; sRs = 1.0 / sqrt(v + 1e-5);
    }
    __syncthreads();
    if (t < CCH) {
        double mu = sMu, rs = sRs;
        sA[t] = (float)((double)g2[t] * rs);
        sB[t] = (float)((double)be2[t] - mu * (double)g2[t] * rs);
    }
    __syncthreads();
    if (blockIdx.x < 25) {
        int idx = blockIdx.x * 256 + t;             // < 6400
        int mtile = idx / 640;
        int rem   = idx % 640;
        int kstep = rem / 32;
        int lane  = rem % 32;
        int g = lane >> 2, tig = lane & 3;
        int m0 = mtile * 16 + g;
        int k0 = kstep * 8 + tig;
        float4 o;
        o.x = rna_tf32(w3[m0 * CCH + k0]       * sA[k0]);
        o.y = rna_tf32(w3[(m0 + 8) * CCH + k0] * sA[k0]);
        o.z = rna_tf32(w3[m0 * CCH + k0 + 4]       * sA[k0 + 4]);
        o.w = rna_tf32(w3[(m0 + 8) * CCH + k0 + 4] * sA[k0 + 4]);
        reinterpret_cast<float4*>(g_Wf)[(size_t)4 * 6400 + idx] = o;
    } else if (t < CCH) {
        float s = b3[t];
        for (int k = 0; k < CCH; ++k) s += w3[t * CCH + k] * sB[k];
        g_b3f[t] = s;
    }
}

__device__ __forceinline__ void stats_reduce(float lsum, float lsq, double* dst) {
    double s = (double)lsum, q = (double)lsq;
    #pragma unroll
    for (int o = 16; o > 0; o >>= 1) {
        s += __shfl_down_sync(0xffffffffu, s, o);
        q += __shfl_down_sync(0xffffffffu, q, o);
    }
    __shared__ double red[32];
    const int w = threadIdx.x >> 5, l = threadIdx.x & 31;
    if (l == 0) { red[w] = s; red[16 + w] = q; }
    __syncthreads();
    if (threadIdx.x == 0) {
        double S = 0.0, Q = 0.0;
        #pragma unroll
        for (int i = 0; i < 12; ++i) { S += red[i]; Q += red[16 + i]; }
        atomicAdd(&dst[0], S);
        atomicAdd(&dst[1], Q);
    }
}

// ---------------- mode 0 / mode 2 GEMM (R8/R11 proven core) ------------------
template<int MODE>
__global__ void __launch_bounds__(NTHR, 1) gemm_mma(
    int gid, const float* __restrict__ Xp,
    const float* __restrict__ bias, float* __restrict__ Outp)
{
    extern __shared__ __align__(16) float smem[];
    float* Ws = smem;
    const uint32_t ws_u = smem_u32(smem);
    const uint32_t bs_u = ws_u + W_FLOATS * 4;

    const int t = threadIdx.x;
    const int lane = t & 31, wid = t >> 5;
    const int warp_m = wid & 1, warp_n = wid >> 1;   // 2 x 6
    const int g = lane >> 2, tig = lane & 3;
    const int bid = blockIdx.x;

    {
        const float* wsrc = g_Wf + (size_t)gid * W_FLOATS;
        #pragma unroll
        for (int i = 0; i < 17; ++i) {
            const int e = t + i * NTHR;
            if (e < 6400)
                cpa16(ws_u + (uint32_t)e * 16, wsrc + (size_t)e * 4, 16);
        }
        CPA_COMMIT();
    }

    const int ntile = (NTILES - bid + GRID_P - 1) / GRID_P;
    const int nq = ntile * 5;
    const float* Bsrc = (MODE == 0) ? Xp : g_y;

    const int r0 = t >> 3;
    const int fj = t & 7;

    auto fill = [&](int q) {
        if (q >= nq) return;
        const int tl = q / 5, kc = q % 5;
        const int tileN = (bid + tl * GRID_P) * BN;
        const uint32_t dbase = bs_u + (uint32_t)(q & 3) * (STAGE_F * 4);
        if (MODE == 0) {
            #pragma unroll
            for (int i = 0; i < 4; ++i) {
                const int e = t + i * NTHR;
                const int k = e / 48, c4 = e % 48;
                cpa16(dbase + (uint32_t)(k * S0 + c4 * 4) * 4,
                      Bsrc + (size_t)(kc * 32 + k) * NT + tileN + c4 * 4, 16);
            }
        } else {
            #pragma unroll
            for (int i = 0; i < 4; ++i) {
                const int r = r0 + i * 48;
                cpa16(dbase + (uint32_t)(r * 36 + fj * 4) * 4,
                      Bsrc + (size_t)(tileN + r) * CCH + kc * 32 + fj * 4, 16);
            }
        }
    };

    fill(0); CPA_COMMIT();
    fill(1); CPA_COMMIT();
    fill(2); CPA_COMMIT();

    float acc[5][4][4];
    #pragma unroll
    for (int mt = 0; mt < 5; ++mt)
        #pragma unroll
        for (int nt = 0; nt < 4; ++nt)
            #pragma unroll
            for (int j = 0; j < 4; ++j) acc[mt][nt][j] = 0.f;
    float lsum = 0.f, lsq = 0.f;

    #pragma unroll 1
    for (int q = 0; q < nq; ++q) {
        CPA_WAIT2();
        __syncthreads();
        fill(q + 3);
        CPA_COMMIT();

        const int kc = q % 5;
        const float* Bb = smem + W_FLOATS + (q & 3) * STAGE_F;

        #pragma unroll
        for (int ksl = 0; ksl < 4; ++ksl) {
            const int ks = kc * 4 + ksl;
            uint4 af[5];
            #pragma unroll
            for (int mt = 0; mt < 5; ++mt)
                af[mt] = *reinterpret_cast<const uint4*>(
                    &Ws[(((warp_m * 5 + mt) * 20 + ks) * 32 + lane) * 4]);
            #pragma unroll
            for (int nt = 0; nt < 4; ++nt) {
                const int nn = warp_n * 32 + nt * 8 + g;
                uint32_t b0, b1;
                if (MODE == 0) {
                    b0 = __float_as_uint(Bb[(ksl * 8 + tig) * S0 + nn]);
                    b1 = __float_as_uint(Bb[(ksl * 8 + tig + 4) * S0 + nn]);
                } else {
                    b0 = __float_as_uint(Bb[nn * 36 + ksl * 8 + tig]);
                    b1 = __float_as_uint(Bb[nn * 36 + ksl * 8 + tig + 4]);
                }
                #pragma unroll
                for (int mt = 0; mt < 5; ++mt)
                    mma8(acc[mt][nt], af[mt], b0, b1);
            }
        }

        if (kc == 4) {
            const int tileN = (bid + (q / 5) * GRID_P) * BN;
            if (MODE == 0) {
                #pragma unroll
                for (int mt = 0; mt < 5; ++mt) {
                    const int m0 = warp_m * 80 + mt * 16 + g;
                    const float bb0 = bias[m0], bb1 = bias[m0 + 8];
                    #pragma unroll
                    for (int nt = 0; nt < 4; ++nt) {
                        const int n0 = tileN + warp_n * 32 + nt * 8 + tig * 2;
                        float v[4];
                        v[0] = acc[mt][nt][0] + bb0;
                        v[1] = acc[mt][nt][1] + bb0;
                        v[2] = acc[mt][nt][2] + bb1;
                        v[3] = acc[mt][nt][3] + bb1;
                        #pragma unroll
                        for (int j = 0; j < 4; ++j) { lsum += v[j]; lsq += v[j] * v[j]; }
                        const size_t a00 = (size_t)n0 * CCH + m0;
                        const size_t a01 = (size_t)(n0 + 1) * CCH + m0;
                        g_h[a00] = v[0]; g_h[a01] = v[1];
                        g_h[a00 + 8] = v[2]; g_h[a01 + 8] = v[3];
                    }
                }
            } else {
                #pragma unroll
                for (int mt = 0; mt < 5; ++mt) {
                    const int m0 = warp_m * 80 + mt * 16 + g;
                    const float bb0 = g_b3f[m0], bb1 = g_b3f[m0 + 8];
                    #pragma unroll
                    for (int nt = 0; nt < 4; ++nt) {
                        const int n0 = tileN + warp_n * 32 + nt * 8 + tig * 2;
                        float2 o0 = {acc[mt][nt][0] + bb0, acc[mt][nt][1] + bb0};
                        float2 o1 = {acc[mt][nt][2] + bb1, acc[mt][nt][3] + bb1};
                        *reinterpret_cast<float2*>(Outp + (size_t)m0 * NT + n0)       = o0;
                        *reinterpret_cast<float2*>(Outp + (size_t)(m0 + 8) * NT + n0) = o1;
                    }
                }
            }
            #pragma unroll
            for (int mt = 0; mt < 5; ++mt)
                #pragma unroll
                for (int nt = 0; nt < 4; ++nt)
                    #pragma unroll
                    for (int j = 0; j < 4; ++j) acc[mt][nt][j] = 0.f;
        }
    }

    if (MODE == 0) stats_reduce(lsum, lsq, &g_stats[0]);
}

// ---------------- fused triple-branch GEMM ------------------------------------
// work item = (n-tile, m-half). Per item: 15 K-chunks (3 branches x 5 kc).
// yv accumulated in registers; single y store + GN2 stats at branch 2.
__global__ void __launch_bounds__(NTHR, 1) gemm_fused(
    const float* __restrict__ b21, const float* __restrict__ b22,
    const float* __restrict__ b23)
{
    extern __shared__ __align__(16) float smem[];
    float* Ws = smem;                                    // 38400 floats (3 x half-W)
    const uint32_t ws_u = smem_u32(smem);
    const uint32_t bs_u = ws_u + FB_W_F * 4;

    const int t = threadIdx.x;
    const int lane = t & 31, wid = t >> 5;               // wid = warp_n (0..11)
    const int g = lane >> 2, tig = lane & 3;
    const int bid = blockIdx.x;
    const int mhalf = bid & 1;
    const int tidx0 = bid >> 1;                          // first n-tile

    // W fill: mhalf slices of w21,w22,w23 (gids 1..3), 9600 float4
    {
        #pragma unroll
        for (int br = 0; br < 3; ++br) {
            const float* wsrc = g_Wf + (size_t)(br + 1) * W_FLOATS
                              + (size_t)mhalf * FB_WHALF_F;
            #pragma unroll
            for (int i = 0; i < 9; ++i) {
                const int e = t + i * NTHR;
                if (e < 3200)
                    cpa16(ws_u + (uint32_t)(br * 3200 + e) * 16, wsrc + (size_t)e * 4, 16);
            }
        }
        CPA_COMMIT();
    }

    const int nitems = (NTILES - tidx0 + 147) / 148;
    const int nq = nitems * 15;

    const int r0 = t >> 3;
    const int fj = t & 7;

    const float* sb[4];
    int si[4];

    auto fill = [&](int q) {
        if (q >= nq) return;
        const int item = q / 15, rem = q % 15;
        const int br = rem / 5, kc = rem % 5;
        const int tileN = (tidx0 + item * 148) * BN;
        const uint32_t dbase = bs_u + (uint32_t)(q & 1) * (STAGE_F * 4);
        const int stride = (br == 0) ? HWS : ((br == 1) ? WS : 1);
        if (kc == 0) {
            #pragma unroll
            for (int i = 0; i < 4; ++i) {
                const int n = tileN + r0 + i * 48;
                si[i] = (br == 0) ? (n / HWS) : ((br == 1) ? ((n / WS) % WS) : (n % WS));
                sb[i] = g_h + (size_t)(n + 2 * stride) * CCH + fj * 4;
            }
        }
        const ptrdiff_t koff = (ptrdiff_t)kc * ((ptrdiff_t)32 - (ptrdiff_t)stride * CCH);
        #pragma unroll
        for (int i = 0; i < 4; ++i) {
            const int r = r0 + i * 48;
            const int sz = ((unsigned)(si[i] + 2 - kc) < (unsigned)WS) ? 16 : 0;
            cpa16(dbase + (uint32_t)(r * 36 + fj * 4) * 4, sb[i] + koff, sz);
        }
    };

    fill(0); CPA_COMMIT();
    fill(1); CPA_COMMIT();

    float acc[5][2][4], yv[5][2][4];
    #pragma unroll
    for (int mt = 0; mt < 5; ++mt)
        #pragma unroll
        for (int nt = 0; nt < 2; ++nt)
            #pragma unroll
            for (int j = 0; j < 4; ++j) { acc[mt][nt][j] = 0.f; yv[mt][nt][j] = 0.f; }
    float lsum = 0.f, lsq = 0.f;

    #pragma unroll 1
    for (int q = 0; q < nq; ++q) {
        CPA_WAIT1();
        __syncthreads();
        const int rem = q % 15;
        const int br = rem / 5, kc = rem % 5;
        const float* Bb = smem + FB_W_F + (q & 1) * STAGE_F;

        #pragma unroll
        for (int ksl = 0; ksl < 4; ++ksl) {
            const int ks = kc * 4 + ksl;
            uint4 af[5];
            #pragma unroll
            for (int mt = 0; mt < 5; ++mt)
                af[mt] = *reinterpret_cast<const uint4*>(
                    &Ws[(br * 3200 + (mt * 20 + ks) * 32 + lane) * 4]);
            #pragma unroll
            for (int nt = 0; nt < 2; ++nt) {
                const int nn = wid * 16 + nt * 8 + g;
                const uint32_t b0 = __float_as_uint(Bb[nn * 36 + ksl * 8 + tig]);
                const uint32_t b1 = __float_as_uint(Bb[nn * 36 + ksl * 8 + tig + 4]);
                #pragma unroll
                for (int mt = 0; mt < 5; ++mt)
                    mma8(acc[mt][nt], af[mt], b0, b1);
            }
        }

        __syncthreads();          // stage (q&1) fully consumed
        fill(q + 2);
        CPA_COMMIT();

        if (kc == 4) {
            const float* bias = (br == 0) ? b21 : ((br == 1) ? b22 : b23);
            #pragma unroll
            for (int mt = 0; mt < 5; ++mt) {
                const int m0 = mhalf * 80 + mt * 16 + g;
                const float bb0 = bias[m0], bb1 = bias[m0 + 8];
                #pragma unroll
                for (int nt = 0; nt < 2; ++nt) {
                    yv[mt][nt][0] += gelu_erf(acc[mt][nt][0] + bb0);
                    yv[mt][nt][1] += gelu_erf(acc[mt][nt][1] + bb0);
                    yv[mt][nt][2] += gelu_erf(acc[mt][nt][2] + bb1);
                    yv[mt][nt][3] += gelu_erf(acc[mt][nt][3] + bb1);
                    #pragma unroll
                    for (int j = 0; j < 4; ++j) acc[mt][nt][j] = 0.f;
                }
            }
            if (br == 2) {
                const int tileN = (tidx0 + (q / 15) * 148) * BN;
                #pragma unroll
                for (int mt = 0; mt < 5; ++mt) {
                    const int m0 = mhalf * 80 + mt * 16 + g;
                    #pragma unroll
                    for (int nt = 0; nt < 2; ++nt) {
                        const int n0 = tileN + wid * 16 + nt * 8 + tig * 2;
                        float v[4];
                        #pragma unroll
                        for (int j = 0; j < 4; ++j) {
                            v[j] = yv[mt][nt][j];
                            lsum += v[j]; lsq += v[j] * v[j];
                            v[j] = rna_tf32(v[j]);
                            yv[mt][nt][j] = 0.f;
                        }
                        const size_t a00 = (size_t)n0 * CCH + m0;
                        const size_t a01 = (size_t)(n0 + 1) * CCH + m0;
                        g_y[a00] = v[0]; g_y[a01] = v[1];
                        g_y[a00 + 8] = v[2]; g_y[a01 + 8] = v[3];
                    }
                }
            }
        }
    }

    stats_reduce(lsum, lsq, &g_stats[2]);
}

// ---------------- launcher ----------------
extern "C" void kernel_launch(void* const* d_in, const int* in_sizes, int n_in,
                              void* d_out, int out_size) {
    const float* x   = (const float*)d_in[0];
    const float* w1  = (const float*)d_in[1];
    const float* b1  = (const float*)d_in[2];
    const float* g1  = (const float*)d_in[3];
    const float* be1 = (const float*)d_in[4];
    const float* w21 = (const float*)d_in[5];
    const float* b21 = (const float*)d_in[6];
    const float* w22 = (const float*)d_in[7];
    const float* b22 = (const float*)d_in[8];
    const float* w23 = (const float*)d_in[9];
    const float* b23 = (const float*)d_in[10];
    const float* g2  = (const float*)d_in[11];
    const float* be2 = (const float*)d_in[12];
    const float* w3  = (const float*)d_in[13];
    const float* b3  = (const float*)d_in[14];
    float* out = (float*)d_out;

    cudaFuncSetAttribute(gemm_mma<0>, cudaFuncAttributeMaxDynamicSharedMemorySize, SMEM_BYTES);
    cudaFuncSetAttribute(gemm_mma<2>, cudaFuncAttributeMaxDynamicSharedMemorySize, SMEM_BYTES);
    cudaFuncSetAttribute(gemm_fused,  cudaFuncAttributeMaxDynamicSharedMemorySize, FB_SMEM);

    prep_w<<<dim3(25, 4), 256>>>(w1, w21, w22, w23);

    gemm_mma<0><<<GRID_P, NTHR, SMEM_BYTES>>>(0, x, b1, nullptr);
    gelu_fin<<<(int)(((size_t)NT * CCH / 4) / 256), 256>>>(g1, be1);

    gemm_fused<<<FB_GRID, NTHR, FB_SMEM>>>(b21, b22, b23);
    final_prep<<<26, 256>>>(w3, b3, g2, be2);

    gemm_mma<2><<<GRID_P, NTHR, SMEM_BYTES>>>(4, nullptr, b3, out);
}

// round 14
// speedup vs baseline: 1.1910x; 1.0940x over previous
#include <cuda_runtime.h>
#include <math.h>
#include <stdint.h>
#include <stddef.h>

#define CCH 160
#define NT  110592          // 48*48*48
#define HWS 2304
#define WS  48
#define BN  192
#define NTILES (NT / BN)    // 576
#define GRID_P 148          // persistent CTAs
#define NTHR 384            // 12 warps: 2(M) x 6(N)

#define W_FLOATS  (CCH * CCH)        // 25600
#define STAGE_F   (BN * 36)          // 6912 floats per stage
#define S0        200                // mode-0 [k][n] stage stride (192 + 8)
#define NSTAGE    4
#define SMEM_FLOATS (W_FLOATS + NSTAGE * STAGE_F)   // 53248
#define SMEM_BYTES  (SMEM_FLOATS * 4)               // 212992

// ---------------- device globals (scratch; no allocation allowed) -------------
__device__ __align__(16) float g_h [(size_t)NT * CCH];   // h0 then h1 in place, [n][c]
__device__ __align__(16) float g_y [(size_t)NT * CCH];   // branch sum, [n][c]
__device__ __align__(16) float g_Wf[5 * W_FLOATS];       // fragment-ordered weights
__device__ float  g_b3f[CCH];                            // folded bias for final GEMM
__device__ double g_stats[4];
__device__ float g_alpha1[CCH], g_beta1[CCH];
__device__ float g_alpha2[CCH], g_beta2[CCH];

// ---------------- helpers ----------------
__device__ __forceinline__ float gelu_erf(float t) {
    return 0.5f * t * (1.0f + erff(t * 0.70710678118654752f));
}
__device__ __forceinline__ float rna_tf32(float x) {
    float r; asm("cvt.rna.tf32.f32 %0, %1;" : "=f"(r) : "f"(x)); return r;
}
__device__ __forceinline__ void mma8(float* c, uint4 a, uint32_t b0, uint32_t b1) {
    asm("mma.sync.aligned.m16n8k8.row.col.f32.tf32.tf32.f32 "
        "{%0,%1,%2,%3}, {%4,%5,%6,%7}, {%8,%9}, {%0,%1,%2,%3};"
        : "+f"(c[0]), "+f"(c[1]), "+f"(c[2]), "+f"(c[3])
        : "r"(a.x), "r"(a.y), "r"(a.z), "r"(a.w), "r"(b0), "r"(b1));
}
__device__ __forceinline__ uint32_t smem_u32(const void* p) {
    uint32_t a;
    asm("{ .reg .u64 t; cvta.to.shared.u64 t, %1; cvt.u32.u64 %0, t; }" : "=r"(a) : "l"(p));
    return a;
}
__device__ __forceinline__ void cpa16(uint32_t dst, const void* src, int sz) {
    asm volatile("cp.async.ca.shared.global [%0], [%1], 16, %2;"
                 :: "r"(dst), "l"(src), "r"(sz) : "memory");
}
#define CPA_COMMIT() asm volatile("cp.async.commit_group;" ::: "memory")
#define CPA_WAIT2()  asm volatile("cp.async.wait_group 2;" ::: "memory")

// ---------------- tiny kernels (R8-style separate glue) ----------------------
__global__ void zero_stats_kernel() {
    if (threadIdx.x < 4) g_stats[threadIdx.x] = 0.0;
}

__global__ void finalize_kernel(int stage, const float* __restrict__ g,
                                const float* __restrict__ be) {
    __shared__ double sh[2];
    if (threadIdx.x == 0) {
        double Nd = (double)CCH * (double)NT;
        double m  = g_stats[stage * 2] / Nd;
        double v  = g_stats[stage * 2 + 1] / Nd - m * m;
        sh[0] = m; sh[1] = 1.0 / sqrt(v + 1e-5);
    }
    __syncthreads();
    const int c = threadIdx.x;
    double mu = sh[0], rs = sh[1];
    float a = (float)((double)g[c] * rs);
    float b = (float)((double)be[c] - mu * (double)g[c] * rs);
    if (stage == 0) { g_alpha1[c] = a; g_beta1[c] = b; }
    else            { g_alpha2[c] = a; g_beta2[c] = b; }
}

// fragment-order + tf32-round weights (gids 0..3: w1,w21,w22,w23)
__global__ void prep_w(const float* __restrict__ w1, const float* __restrict__ w21,
                       const float* __restrict__ w22, const float* __restrict__ w23) {
    const int gid = blockIdx.y;
    const float* W = (gid == 0) ? w1 : (gid == 1) ? w21 : (gid == 2) ? w22 : w23;
    int idx = blockIdx.x * 256 + threadIdx.x;       // < 6400
    if (idx >= 6400) return;
    int mtile = idx / 640;
    int rem   = idx % 640;
    int kstep = rem / 32;
    int lane  = rem % 32;
    int g = lane >> 2, tig = lane & 3;
    int m0 = mtile * 16 + g;
    int k0 = kstep * 8 + tig;
    float4 o;
    o.x = rna_tf32(W[m0 * CCH + k0]);
    o.y = rna_tf32(W[(m0 + 8) * CCH + k0]);
    o.z = rna_tf32(W[m0 * CCH + k0 + 4]);
    o.w = rna_tf32(W[(m0 + 8) * CCH + k0 + 4]);
    reinterpret_cast<float4*>(g_Wf)[(size_t)gid * 6400 + idx] = o;
}

// w3 with GN2 alpha folded into columns, fragment-ordered into gid slot 4
__global__ void prep_w3(const float* __restrict__ w3) {
    int idx = blockIdx.x * 256 + threadIdx.x;
    if (idx >= 6400) return;
    int mtile = idx / 640;
    int rem   = idx % 640;
    int kstep = rem / 32;
    int lane  = rem % 32;
    int g = lane >> 2, tig = lane & 3;
    int m0 = mtile * 16 + g;
    int k0 = kstep * 8 + tig;
    float4 o;
    o.x = rna_tf32(w3[m0 * CCH + k0]       * g_alpha2[k0]);
    o.y = rna_tf32(w3[(m0 + 8) * CCH + k0] * g_alpha2[k0]);
    o.z = rna_tf32(w3[m0 * CCH + k0 + 4]       * g_alpha2[k0 + 4]);
    o.w = rna_tf32(w3[(m0 + 8) * CCH + k0 + 4] * g_alpha2[k0 + 4]);
    reinterpret_cast<float4*>(g_Wf)[(size_t)4 * 6400 + idx] = o;
}

// b3' = b3 + w3 @ beta2
__global__ void fold_b3(const float* __restrict__ w3, const float* __restrict__ b3) {
    const int m = threadIdx.x;
    float s = b3[m];
    for (int k = 0; k < CCH; ++k) s += w3[m * CCH + k] * g_beta2[k];
    g_b3f[m] = s;
}

// h1 = rna(gelu(affine1(h0))) in place, [n][c]
__global__ void gelu_pass() {
    size_t i4 = (size_t)blockIdx.x * blockDim.x + threadIdx.x;
    if (i4 >= (size_t)NT * CCH / 4) return;
    const int c0 = (int)((i4 * 4) % CCH);
    float4 v = reinterpret_cast<float4*>(g_h)[i4];
    v.x = rna_tf32(gelu_erf(fmaf(g_alpha1[c0 + 0], v.x, g_beta1[c0 + 0])));
    v.y = rna_tf32(gelu_erf(fmaf(g_alpha1[c0 + 1], v.y, g_beta1[c0 + 1])));
    v.z = rna_tf32(gelu_erf(fmaf(g_alpha1[c0 + 2], v.z, g_beta1[c0 + 2])));
    v.w = rna_tf32(gelu_erf(fmaf(g_alpha1[c0 + 3], v.w, g_beta1[c0 + 3])));
    reinterpret_cast<float4*>(g_h)[i4] = v;
}

__device__ __forceinline__ void stats_reduce(float lsum, float lsq, double* dst) {
    double s = (double)lsum, q = (double)lsq;
    #pragma unroll
    for (int o = 16; o > 0; o >>= 1) {
        s += __shfl_down_sync(0xffffffffu, s, o);
        q += __shfl_down_sync(0xffffffffu, q, o);
    }
    __shared__ double red[32];
    const int w = threadIdx.x >> 5, l = threadIdx.x & 31;
    if (l == 0) { red[w] = s; red[16 + w] = q; }
    __syncthreads();
    if (threadIdx.x == 0) {
        double S = 0.0, Q = 0.0;
        #pragma unroll
        for (int i = 0; i < 12; ++i) { S += red[i]; Q += red[16 + i]; }
        atomicAdd(&dst[0], S);
        atomicAdd(&dst[1], Q);
    }
}

// ---------------- persistent multistage tf32 mma GEMM (R8 core + hoisted shifts)
// MODE 0 : h0 = W1@x  + b1   (B = x direct, [k][n] stage)  -> g_h, GN1 stats
// MODE 10: y  = gelu(W21@sh_d(h1) + b21)    -> g_y store
// MODE 11: y += gelu(W22@sh_h(h1) + b22)    -> g_y RMW
// MODE 12: y += gelu(W23@sh_w(h1) + b23)    -> g_y RMW (rna), GN2 stats
// MODE 2 : out = W3'@y + b3'                -> Outp [c][n]
template<int MODE>
__global__ void __launch_bounds__(NTHR, 1) gemm_mma(
    int gid, const float* __restrict__ Xp,
    const float* __restrict__ bias, float* __restrict__ Outp)
{
    extern __shared__ __align__(16) float smem[];
    float* Ws = smem;
    const uint32_t ws_u = smem_u32(smem);
    const uint32_t bs_u = ws_u + W_FLOATS * 4;

    const int t = threadIdx.x;
    const int lane = t & 31, wid = t >> 5;
    const int warp_m = wid & 1, warp_n = wid >> 1;   // 2 x 6, warp covers 32 cols
    const int g = lane >> 2, tig = lane & 3;
    const int bid = blockIdx.x;

    // W fill (async, first group)
    {
        const float* wsrc = g_Wf + (size_t)gid * W_FLOATS;
        #pragma unroll
        for (int i = 0; i < 17; ++i) {
            const int e = t + i * NTHR;
            if (e < 6400)
                cpa16(ws_u + (uint32_t)e * 16, wsrc + (size_t)e * 4, 16);
        }
        CPA_COMMIT();
    }

    const int ntile = (NTILES - bid + GRID_P - 1) / GRID_P;
    const int nq = ntile * 5;
    const float* Bsrc = (MODE == 0) ? Xp : ((MODE == 2) ? g_y : g_h);

    const int r0 = t >> 3;        // [n][c] fill: rows r0 + i*48  (i<4)
    const int fj = t & 7;         // 16B chunk within 32-ch row

    // shift modes: per-tile hoisted state (recomputed at kc==0; fill q strictly increases)
    const int stride = (MODE == 10) ? HWS : ((MODE == 11) ? WS : 1);
    const ptrdiff_t kdelta = (ptrdiff_t)32 - (ptrdiff_t)stride * CCH;  // src step per kc
    const float* sb0; const float* sb1; const float* sb2; const float* sb3;
    int si0, si1, si2, si3;

    auto fill = [&](int q) {
        if (q >= nq) return;
        const int tl = q / 5, kc = q % 5;
        const int tileN = (bid + tl * GRID_P) * BN;
        const uint32_t dbase = bs_u + (uint32_t)(q & 3) * (STAGE_F * 4);
        if (MODE == 0) {
            #pragma unroll
            for (int i = 0; i < 4; ++i) {
                const int e = t + i * NTHR;           // 0..1535
                const int k = e / 48, c4 = e % 48;    // 48 float4 per row
                cpa16(dbase + (uint32_t)(k * S0 + c4 * 4) * 4,
                      Bsrc + (size_t)(kc * 32 + k) * NT + tileN + c4 * 4, 16);
            }
        } else if (MODE == 2) {
            #pragma unroll
            for (int i = 0; i < 4; ++i) {
                const int r = r0 + i * 48;
                cpa16(dbase + (uint32_t)(r * 36 + fj * 4) * 4,
                      Bsrc + (size_t)(tileN + r) * CCH + kc * 32 + fj * 4, 16);
            }
        } else {
            if (kc == 0) {   // hoist: recompute per-tile bases once per 5 chunks
                #pragma unroll
                for (int i = 0; i < 4; ++i) {
                    const int n = tileN + r0 + i * 48;
                    const int idx = (MODE == 10) ? (n / HWS)
                                  : (MODE == 11) ? ((n / WS) % WS) : (n % WS);
                    const float* sb = Bsrc + (size_t)(n + 2 * stride) * CCH + fj * 4;
                    if (i == 0) { sb0 = sb; si0 = idx; }
                    if (i == 1) { sb1 = sb; si1 = idx; }
                    if (i == 2) { sb2 = sb; si2 = idx; }
                    if (i == 3) { sb3 = sb; si3 = idx; }
                }
            }
            const ptrdiff_t koff = (ptrdiff_t)kc * kdelta;
            #pragma unroll
            for (int i = 0; i < 4; ++i) {
                const int r = r0 + i * 48;
                const float* sb = (i == 0) ? sb0 : (i == 1) ? sb1 : (i == 2) ? sb2 : sb3;
                const int si    = (i == 0) ? si0 : (i == 1) ? si1 : (i == 2) ? si2 : si3;
                const int sz = ((unsigned)(si + 2 - kc) < (unsigned)WS) ? 16 : 0;
                cpa16(dbase + (uint32_t)(r * 36 + fj * 4) * 4, sb + koff, sz);
            }
        }
    };

    fill(0); CPA_COMMIT();
    fill(1); CPA_COMMIT();
    fill(2); CPA_COMMIT();

    float acc[5][4][4];
    #pragma unroll
    for (int mt = 0; mt < 5; ++mt)
        #pragma unroll
        for (int nt = 0; nt < 4; ++nt)
            #pragma unroll
            for (int j = 0; j < 4; ++j) acc[mt][nt][j] = 0.f;
    float lsum = 0.f, lsq = 0.f;

    #pragma unroll 1
    for (int q = 0; q < nq; ++q) {
        CPA_WAIT2();
        __syncthreads();
        // safe: stage (q+3)&3 == (q-1)&3 was last read in iter q-1; sync above fences it
        fill(q + 3);
        CPA_COMMIT();

        const int kc = q % 5;
        const float* Bb = smem + W_FLOATS + (q & 3) * STAGE_F;

        #pragma unroll
        for (int ksl = 0; ksl < 4; ++ksl) {
            const int ks = kc * 4 + ksl;
            uint4 af[5];
            #pragma unroll
            for (int mt = 0; mt < 5; ++mt)
                af[mt] = *reinterpret_cast<const uint4*>(
                    &Ws[(((warp_m * 5 + mt) * 20 + ks) * 32 + lane) * 4]);
            #pragma unroll
            for (int nt = 0; nt < 4; ++nt) {
                const int nn = warp_n * 32 + nt * 8 + g;
                uint32_t b0, b1;
                if (MODE == 0) {
                    b0 = __float_as_uint(Bb[(ksl * 8 + tig) * S0 + nn]);
                    b1 = __float_as_uint(Bb[(ksl * 8 + tig + 4) * S0 + nn]);
                } else {
                    b0 = __float_as_uint(Bb[nn * 36 + ksl * 8 + tig]);
                    b1 = __float_as_uint(Bb[nn * 36 + ksl * 8 + tig + 4]);
                }
                #pragma unroll
                for (int mt = 0; mt < 5; ++mt)
                    mma8(acc[mt][nt], af[mt], b0, b1);
            }
        }

        if (kc == 4) {
            // ---- tile epilogue ----
            const int tileN = (bid + (q / 5) * GRID_P) * BN;
            if (MODE != 2) {
                #pragma unroll
                for (int mt = 0; mt < 5; ++mt) {
                    const int m0 = warp_m * 80 + mt * 16 + g;
                    const float bb0 = bias[m0], bb1 = bias[m0 + 8];
                    #pragma unroll
                    for (int nt = 0; nt < 4; ++nt) {
                        const int n0 = tileN + warp_n * 32 + nt * 8 + tig * 2;
                        float v[4];
                        v[0] = acc[mt][nt][0] + bb0;
                        v[1] = acc[mt][nt][1] + bb0;
                        v[2] = acc[mt][nt][2] + bb1;
                        v[3] = acc[mt][nt][3] + bb1;
                        const size_t a00 = (size_t)n0 * CCH + m0;
                        const size_t a01 = (size_t)(n0 + 1) * CCH + m0;
                        if (MODE == 0) {
                            #pragma unroll
                            for (int j = 0; j < 4; ++j) { lsum += v[j]; lsq += v[j] * v[j]; }
                            g_h[a00] = v[0]; g_h[a01] = v[1];
                            g_h[a00 + 8] = v[2]; g_h[a01 + 8] = v[3];
                        } else {
                            #pragma unroll
                            for (int j = 0; j < 4; ++j) v[j] = gelu_erf(v[j]);
                            if (MODE != 10) {
                                v[0] += g_y[a00]; v[1] += g_y[a01];
                                v[2] += g_y[a00 + 8]; v[3] += g_y[a01 + 8];
                            }
                            if (MODE == 12) {
                                #pragma unroll
                                for (int j = 0; j < 4; ++j) {
                                    lsum += v[j]; lsq += v[j] * v[j];
                                    v[j] = rna_tf32(v[j]);     // final y, pre-rounded for GEMM 2
                                }
                            }
                            g_y[a00] = v[0]; g_y[a01] = v[1];
                            g_y[a00 + 8] = v[2]; g_y[a01 + 8] = v[3];
                        }
                    }
                }
            } else {
                #pragma unroll
                for (int mt = 0; mt < 5; ++mt) {
                    const int m0 = warp_m * 80 + mt * 16 + g;
                    const float bb0 = g_b3f[m0], bb1 = g_b3f[m0 + 8];
                    #pragma unroll
                    for (int nt = 0; nt < 4; ++nt) {
                        const int n0 = tileN + warp_n * 32 + nt * 8 + tig * 2;
                        float2 o0 = {acc[mt][nt][0] + bb0, acc[mt][nt][1] + bb0};
                        float2 o1 = {acc[mt][nt][2] + bb1, acc[mt][nt][3] + bb1};
                        *reinterpret_cast<float2*>(Outp + (size_t)m0 * NT + n0)       = o0;
                        *reinterpret_cast<float2*>(Outp + (size_t)(m0 + 8) * NT + n0) = o1;
                    }
                }
            }
            #pragma unroll
            for (int mt = 0; mt < 5; ++mt)
                #pragma unroll
                for (int nt = 0; nt < 4; ++nt)
                    #pragma unroll
                    for (int j = 0; j < 4; ++j) acc[mt][nt][j] = 0.f;
        }
    }

    if (MODE == 0)  stats_reduce(lsum, lsq, &g_stats[0]);
    if (MODE == 12) stats_reduce(lsum, lsq, &g_stats[2]);
}

// ---------------- launcher (R8-style, 12 launches) ----------------------------
extern "C" void kernel_launch(void* const* d_in, const int* in_sizes, int n_in,
                              void* d_out, int out_size) {
    const float* x   = (const float*)d_in[0];
    const float* w1  = (const float*)d_in[1];
    const float* b1  = (const float*)d_in[2];
    const float* g1  = (const float*)d_in[3];
    const float* be1 = (const float*)d_in[4];
    const float* w21 = (const float*)d_in[5];
    const float* b21 = (const float*)d_in[6];
    const float* w22 = (const float*)d_in[7];
    const float* b22 = (const float*)d_in[8];
    const float* w23 = (const float*)d_in[9];
    const float* b23 = (const float*)d_in[10];
    const float* g2  = (const float*)d_in[11];
    const float* be2 = (const float*)d_in[12];
    const float* w3  = (const float*)d_in[13];
    const float* b3  = (const float*)d_in[14];
    float* out = (float*)d_out;

    cudaFuncSetAttribute(gemm_mma<0>,  cudaFuncAttributeMaxDynamicSharedMemorySize, SMEM_BYTES);
    cudaFuncSetAttribute(gemm_mma<10>, cudaFuncAttributeMaxDynamicSharedMemorySize, SMEM_BYTES);
    cudaFuncSetAttribute(gemm_mma<11>, cudaFuncAttributeMaxDynamicSharedMemorySize, SMEM_BYTES);
    cudaFuncSetAttribute(gemm_mma<12>, cudaFuncAttributeMaxDynamicSharedMemorySize, SMEM_BYTES);
    cudaFuncSetAttribute(gemm_mma<2>,  cudaFuncAttributeMaxDynamicSharedMemorySize, SMEM_BYTES);

    zero_stats_kernel<<<1, 32>>>();
    prep_w<<<dim3(25, 4), 256>>>(w1, w21, w22, w23);

    gemm_mma<0><<<GRID_P, NTHR, SMEM_BYTES>>>(0, x, b1, nullptr);
    finalize_kernel<<<1, CCH>>>(0, g1, be1);
    gelu_pass<<<(int)(((size_t)NT * CCH / 4 + 255) / 256), 256>>>();

    gemm_mma<10><<<GRID_P, NTHR, SMEM_BYTES>>>(1, nullptr, b21, nullptr);
    gemm_mma<11><<<GRID_P, NTHR, SMEM_BYTES>>>(2, nullptr, b22, nullptr);
    gemm_mma<12><<<GRID_P, NTHR, SMEM_BYTES>>>(3, nullptr, b23, nullptr);
    finalize_kernel<<<1, CCH>>>(1, g2, be2);
    prep_w3<<<25, 256>>>(w3);
    fold_b3<<<1, CCH>>>(w3, b3);

    gemm_mma<2><<<GRID_P, NTHR, SMEM_BYTES>>>(4, nullptr, b3, out);
}

// round 15
// speedup vs baseline: 1.1931x; 1.0018x over previous
#include <cuda_runtime.h>
#include <math.h>
#include <stdint.h>
#include <stddef.h>

#define CCH 160
#define NT  110592          // 48*48*48
#define HWS 2304
#define WS  48
#define BN  192
#define NTILES (NT / BN)    // 576
#define GRID_P 148          // persistent CTAs
#define NTHR 384            // 12 warps: 2(M) x 6(N)

#define W_FLOATS  (CCH * CCH)        // 25600
#define STAGE_F   (BN * 36)          // 6912 floats per stage
#define S0        200                // mode-0 [k][n] stage stride (192 + 8)
#define NSTAGE    4
#define SMEM_FLOATS (W_FLOATS + NSTAGE * STAGE_F)   // 53248
#define SMEM_BYTES  (SMEM_FLOATS * 4)               // 212992

// ---------------- device globals (scratch; no allocation allowed) -------------
__device__ __align__(16) float g_h [(size_t)NT * CCH];   // h0 then h1 in place, [n][c]
__device__ __align__(16) float g_y [(size_t)NT * CCH];   // branch sum, [n][c]
__device__ __align__(16) float g_Wf[5 * W_FLOATS];       // fragment-ordered weights
__device__ float  g_b3f[CCH];                            // folded bias for final GEMM
__device__ double g_stats[4];
__device__ float g_alpha1[CCH], g_beta1[CCH];
__device__ float g_alpha2[CCH], g_beta2[CCH];

// ---------------- helpers ----------------
__device__ __forceinline__ float gelu_erf(float t) {
    return 0.5f * t * (1.0f + erff(t * 0.70710678118654752f));
}
__device__ __forceinline__ float rna_tf32(float x) {
    float r; asm("cvt.rna.tf32.f32 %0, %1;" : "=f"(r) : "f"(x)); return r;
}
__device__ __forceinline__ void mma8(float* c, uint4 a, uint32_t b0, uint32_t b1) {
    asm("mma.sync.aligned.m16n8k8.row.col.f32.tf32.tf32.f32 "
        "{%0,%1,%2,%3}, {%4,%5,%6,%7}, {%8,%9}, {%0,%1,%2,%3};"
        : "+f"(c[0]), "+f"(c[1]), "+f"(c[2]), "+f"(c[3])
        : "r"(a.x), "r"(a.y), "r"(a.z), "r"(a.w), "r"(b0), "r"(b1));
}
__device__ __forceinline__ uint32_t smem_u32(const void* p) {
    uint32_t a;
    asm("{ .reg .u64 t; cvta.to.shared.u64 t, %1; cvt.u32.u64 %0, t; }" : "=r"(a) : "l"(p));
    return a;
}
__device__ __forceinline__ void cpa16(uint32_t dst, const void* src, int sz) {
    asm volatile("cp.async.ca.shared.global [%0], [%1], 16, %2;"
                 :: "r"(dst), "l"(src), "r"(sz) : "memory");
}
#define CPA_COMMIT() asm volatile("cp.async.commit_group;" ::: "memory")
#define CPA_WAIT2()  asm volatile("cp.async.wait_group 2;" ::: "memory")

// ---------------- tiny kernels (R14-style separate glue) ----------------------
__global__ void zero_stats_kernel() {
    if (threadIdx.x < 4) g_stats[threadIdx.x] = 0.0;
}

__global__ void finalize_kernel(int stage, const float* __restrict__ g,
                                const float* __restrict__ be) {
    __shared__ double sh[2];
    if (threadIdx.x == 0) {
        double Nd = (double)CCH * (double)NT;
        double m  = g_stats[stage * 2] / Nd;
        double v  = g_stats[stage * 2 + 1] / Nd - m * m;
        sh[0] = m; sh[1] = 1.0 / sqrt(v + 1e-5);
    }
    __syncthreads();
    const int c = threadIdx.x;
    double mu = sh[0], rs = sh[1];
    float a = (float)((double)g[c] * rs);
    float b = (float)((double)be[c] - mu * (double)g[c] * rs);
    if (stage == 0) { g_alpha1[c] = a; g_beta1[c] = b; }
    else            { g_alpha2[c] = a; g_beta2[c] = b; }
}

// fragment-order + tf32-round weights (gids 0..3: w1,w21,w22,w23)
__global__ void prep_w(const float* __restrict__ w1, const float* __restrict__ w21,
                       const float* __restrict__ w22, const float* __restrict__ w23) {
    const int gid = blockIdx.y;
    const float* W = (gid == 0) ? w1 : (gid == 1) ? w21 : (gid == 2) ? w22 : w23;
    int idx = blockIdx.x * 256 + threadIdx.x;       // < 6400
    if (idx >= 6400) return;
    int mtile = idx / 640;
    int rem   = idx % 640;
    int kstep = rem / 32;
    int lane  = rem % 32;
    int g = lane >> 2, tig = lane & 3;
    int m0 = mtile * 16 + g;
    int k0 = kstep * 8 + tig;
    float4 o;
    o.x = rna_tf32(W[m0 * CCH + k0]);
    o.y = rna_tf32(W[(m0 + 8) * CCH + k0]);
    o.z = rna_tf32(W[m0 * CCH + k0 + 4]);
    o.w = rna_tf32(W[(m0 + 8) * CCH + k0 + 4]);
    reinterpret_cast<float4*>(g_Wf)[(size_t)gid * 6400 + idx] = o;
}

// w3 with GN2 alpha folded into columns, fragment-ordered into gid slot 4
__global__ void prep_w3(const float* __restrict__ w3) {
    int idx = blockIdx.x * 256 + threadIdx.x;
    if (idx >= 6400) return;
    int mtile = idx / 640;
    int rem   = idx % 640;
    int kstep = rem / 32;
    int lane  = rem % 32;
    int g = lane >> 2, tig = lane & 3;
    int m0 = mtile * 16 + g;
    int k0 = kstep * 8 + tig;
    float4 o;
    o.x = rna_tf32(w3[m0 * CCH + k0]       * g_alpha2[k0]);
    o.y = rna_tf32(w3[(m0 + 8) * CCH + k0] * g_alpha2[k0]);
    o.z = rna_tf32(w3[m0 * CCH + k0 + 4]       * g_alpha2[k0 + 4]);
    o.w = rna_tf32(w3[(m0 + 8) * CCH + k0 + 4] * g_alpha2[k0 + 4]);
    reinterpret_cast<float4*>(g_Wf)[(size_t)4 * 6400 + idx] = o;
}

// b3' = b3 + w3 @ beta2
__global__ void fold_b3(const float* __restrict__ w3, const float* __restrict__ b3) {
    const int m = threadIdx.x;
    float s = b3[m];
    for (int k = 0; k < CCH; ++k) s += w3[m * CCH + k] * g_beta2[k];
    g_b3f[m] = s;
}

// h1 = rna(gelu(affine1(h0))) in place, [n][c].
// Index-math-free inner loop: 240 thr, thread owns fixed channel c0 = (t%40)*4;
// block covers 48 rows (t/40 gives row phase 0..5, 8 iters of stride 6).
__global__ void __launch_bounds__(240) gelu_pass() {
    const int t = threadIdx.x;
    const int r_off = t / 40;          // 0..5
    const int c4    = t % 40;          // 0..39
    const int c0    = c4 * 4;
    const float4 al = *reinterpret_cast<const float4*>(&g_alpha1[c0]);
    const float4 bt = *reinterpret_cast<const float4*>(&g_beta1[c0]);
    const int rbase = blockIdx.x * 48 + r_off;
    #pragma unroll
    for (int i = 0; i < 8; ++i) {
        const size_t r = (size_t)(rbase + i * 6);
        float4* p = reinterpret_cast<float4*>(g_h + r * CCH + c0);
        float4 v = *p;
        v.x = rna_tf32(gelu_erf(fmaf(al.x, v.x, bt.x)));
        v.y = rna_tf32(gelu_erf(fmaf(al.y, v.y, bt.y)));
        v.z = rna_tf32(gelu_erf(fmaf(al.z, v.z, bt.z)));
        v.w = rna_tf32(gelu_erf(fmaf(al.w, v.w, bt.w)));
        *p = v;
    }
}

__device__ __forceinline__ void stats_reduce(float lsum, float lsq, double* dst) {
    double s = (double)lsum, q = (double)lsq;
    #pragma unroll
    for (int o = 16; o > 0; o >>= 1) {
        s += __shfl_down_sync(0xffffffffu, s, o);
        q += __shfl_down_sync(0xffffffffu, q, o);
    }
    __shared__ double red[32];
    const int w = threadIdx.x >> 5, l = threadIdx.x & 31;
    if (l == 0) { red[w] = s; red[16 + w] = q; }
    __syncthreads();
    if (threadIdx.x == 0) {
        double S = 0.0, Q = 0.0;
        #pragma unroll
        for (int i = 0; i < 12; ++i) { S += red[i]; Q += red[16 + i]; }
        atomicAdd(&dst[0], S);
        atomicAdd(&dst[1], Q);
    }
}

// ---------------- persistent multistage tf32 mma GEMM (R14 core, unchanged) --
// MODE 0 : h0 = W1@x  + b1   (B = x direct, [k][n] stage)  -> g_h, GN1 stats
// MODE 10: y  = gelu(W21@sh_d(h1) + b21)    -> g_y store
// MODE 11: y += gelu(W22@sh_h(h1) + b22)    -> g_y RMW
// MODE 12: y += gelu(W23@sh_w(h1) + b23)    -> g_y RMW (rna), GN2 stats
// MODE 2 : out = W3'@y + b3'                -> Outp [c][n]
template<int MODE>
__global__ void __launch_bounds__(NTHR, 1) gemm_mma(
    int gid, const float* __restrict__ Xp,
    const float* __restrict__ bias, float* __restrict__ Outp)
{
    extern __shared__ __align__(16) float smem[];
    float* Ws = smem;
    const uint32_t ws_u = smem_u32(smem);
    const uint32_t bs_u = ws_u + W_FLOATS * 4;

    const int t = threadIdx.x;
    const int lane = t & 31, wid = t >> 5;
    const int warp_m = wid & 1, warp_n = wid >> 1;   // 2 x 6, warp covers 32 cols
    const int g = lane >> 2, tig = lane & 3;
    const int bid = blockIdx.x;

    // W fill (async, first group)
    {
        const float* wsrc = g_Wf + (size_t)gid * W_FLOATS;
        #pragma unroll
        for (int i = 0; i < 17; ++i) {
            const int e = t + i * NTHR;
            if (e < 6400)
                cpa16(ws_u + (uint32_t)e * 16, wsrc + (size_t)e * 4, 16);
        }
        CPA_COMMIT();
    }

    const int ntile = (NTILES - bid + GRID_P - 1) / GRID_P;
    const int nq = ntile * 5;
    const float* Bsrc = (MODE == 0) ? Xp : ((MODE == 2) ? g_y : g_h);

    const int r0 = t >> 3;        // [n][c] fill: rows r0 + i*48  (i<4)
    const int fj = t & 7;         // 16B chunk within 32-ch row

    // shift modes: per-tile hoisted state (recomputed at kc==0; fill q strictly increases)
    const int stride = (MODE == 10) ? HWS : ((MODE == 11) ? WS : 1);
    const ptrdiff_t kdelta = (ptrdiff_t)32 - (ptrdiff_t)stride * CCH;  // src step per kc
    const float* sb0; const float* sb1; const float* sb2; const float* sb3;
    int si0, si1, si2, si3;

    auto fill = [&](int q) {
        if (q >= nq) return;
        const int tl = q / 5, kc = q % 5;
        const int tileN = (bid + tl * GRID_P) * BN;
        const uint32_t dbase = bs_u + (uint32_t)(q & 3) * (STAGE_F * 4);
        if (MODE == 0) {
            #pragma unroll
            for (int i = 0; i < 4; ++i) {
                const int e = t + i * NTHR;           // 0..1535
                const int k = e / 48, c4 = e % 48;    // 48 float4 per row
                cpa16(dbase + (uint32_t)(k * S0 + c4 * 4) * 4,
                      Bsrc + (size_t)(kc * 32 + k) * NT + tileN + c4 * 4, 16);
            }
        } else if (MODE == 2) {
            #pragma unroll
            for (int i = 0; i < 4; ++i) {
                const int r = r0 + i * 48;
                cpa16(dbase + (uint32_t)(r * 36 + fj * 4) * 4,
                      Bsrc + (size_t)(tileN + r) * CCH + kc * 32 + fj * 4, 16);
            }
        } else {
            if (kc == 0) {   // hoist: recompute per-tile bases once per 5 chunks
                #pragma unroll
                for (int i = 0; i < 4; ++i) {
                    const int n = tileN + r0 + i * 48;
                    const int idx = (MODE == 10) ? (n / HWS)
                                  : (MODE == 11) ? ((n / WS) % WS) : (n % WS);
                    const float* sb = Bsrc + (size_t)(n + 2 * stride) * CCH + fj * 4;
                    if (i == 0) { sb0 = sb; si0 = idx; }
                    if (i == 1) { sb1 = sb; si1 = idx; }
                    if (i == 2) { sb2 = sb; si2 = idx; }
                    if (i == 3) { sb3 = sb; si3 = idx; }
                }
            }
            const ptrdiff_t koff = (ptrdiff_t)kc * kdelta;
            #pragma unroll
            for (int i = 0; i < 4; ++i) {
                const int r = r0 + i * 48;
                const float* sb = (i == 0) ? sb0 : (i == 1) ? sb1 : (i == 2) ? sb2 : sb3;
                const int si    = (i == 0) ? si0 : (i == 1) ? si1 : (i == 2) ? si2 : si3;
                const int sz = ((unsigned)(si + 2 - kc) < (unsigned)WS) ? 16 : 0;
                cpa16(dbase + (uint32_t)(r * 36 + fj * 4) * 4, sb + koff, sz);
            }
        }
    };

    fill(0); CPA_COMMIT();
    fill(1); CPA_COMMIT();
    fill(2); CPA_COMMIT();

    float acc[5][4][4];
    #pragma unroll
    for (int mt = 0; mt < 5; ++mt)
        #pragma unroll
        for (int nt = 0; nt < 4; ++nt)
            #pragma unroll
            for (int j = 0; j < 4; ++j) acc[mt][nt][j] = 0.f;
    float lsum = 0.f, lsq = 0.f;

    #pragma unroll 1
    for (int q = 0; q < nq; ++q) {
        CPA_WAIT2();
        __syncthreads();
        // safe: stage (q+3)&3 == (q-1)&3 was last read in iter q-1; sync above fences it
        fill(q + 3);
        CPA_COMMIT();

        const int kc = q % 5;
        const float* Bb = smem + W_FLOATS + (q & 3) * STAGE_F;

        #pragma unroll
        for (int ksl = 0; ksl < 4; ++ksl) {
            const int ks = kc * 4 + ksl;
            uint4 af[5];
            #pragma unroll
            for (int mt = 0; mt < 5; ++mt)
                af[mt] = *reinterpret_cast<const uint4*>(
                    &Ws[(((warp_m * 5 + mt) * 20 + ks) * 32 + lane) * 4]);
            #pragma unroll
            for (int nt = 0; nt < 4; ++nt) {
                const int nn = warp_n * 32 + nt * 8 + g;
                uint32_t b0, b1;
                if (MODE == 0) {
                    b0 = __float_as_uint(Bb[(ksl * 8 + tig) * S0 + nn]);
                    b1 = __float_as_uint(Bb[(ksl * 8 + tig + 4) * S0 + nn]);
                } else {
                    b0 = __float_as_uint(Bb[nn * 36 + ksl * 8 + tig]);
                    b1 = __float_as_uint(Bb[nn * 36 + ksl * 8 + tig + 4]);
                }
                #pragma unroll
                for (int mt = 0; mt < 5; ++mt)
                    mma8(acc[mt][nt], af[mt], b0, b1);
            }
        }

        if (kc == 4) {
            // ---- tile epilogue ----
            const int tileN = (bid + (q / 5) * GRID_P) * BN;
            if (MODE != 2) {
                #pragma unroll
                for (int mt = 0; mt < 5; ++mt) {
                    const int m0 = warp_m * 80 + mt * 16 + g;
                    const float bb0 = bias[m0], bb1 = bias[m0 + 8];
                    #pragma unroll
                    for (int nt = 0; nt < 4; ++nt) {
                        const int n0 = tileN + warp_n * 32 + nt * 8 + tig * 2;
                        float v[4];
                        v[0] = acc[mt][nt][0] + bb0;
                        v[1] = acc[mt][nt][1] + bb0;
                        v[2] = acc[mt][nt][2] + bb1;
                        v[3] = acc[mt][nt][3] + bb1;
                        const size_t a00 = (size_t)n0 * CCH + m0;
                        const size_t a01 = (size_t)(n0 + 1) * CCH + m0;
                        if (MODE == 0) {
                            #pragma unroll
                            for (int j = 0; j < 4; ++j) { lsum += v[j]; lsq += v[j] * v[j]; }
                            g_h[a00] = v[0]; g_h[a01] = v[1];
                            g_h[a00 + 8] = v[2]; g_h[a01 + 8] = v[3];
                        } else {
                            #pragma unroll
                            for (int j = 0; j < 4; ++j) v[j] = gelu_erf(v[j]);
                            if (MODE != 10) {
                                v[0] += g_y[a00]; v[1] += g_y[a01];
                                v[2] += g_y[a00 + 8]; v[3] += g_y[a01 + 8];
                            }
                            if (MODE == 12) {
                                #pragma unroll
                                for (int j = 0; j < 4; ++j) {
                                    lsum += v[j]; lsq += v[j] * v[j];
                                    v[j] = rna_tf32(v[j]);     // final y, pre-rounded for GEMM 2
                                }
                            }
                            g_y[a00] = v[0]; g_y[a01] = v[1];
                            g_y[a00 + 8] = v[2]; g_y[a01 + 8] = v[3];
                        }
                    }
                }
            } else {
                #pragma unroll
                for (int mt = 0; mt < 5; ++mt) {
                    const int m0 = warp_m * 80 + mt * 16 + g;
                    const float bb0 = g_b3f[m0], bb1 = g_b3f[m0 + 8];
                    #pragma unroll
                    for (int nt = 0; nt < 4; ++nt) {
                        const int n0 = tileN + warp_n * 32 + nt * 8 + tig * 2;
                        float2 o0 = {acc[mt][nt][0] + bb0, acc[mt][nt][1] + bb0};
                        float2 o1 = {acc[mt][nt][2] + bb1, acc[mt][nt][3] + bb1};
                        *reinterpret_cast<float2*>(Outp + (size_t)m0 * NT + n0)       = o0;
                        *reinterpret_cast<float2*>(Outp + (size_t)(m0 + 8) * NT + n0) = o1;
                    }
                }
            }
            #pragma unroll
            for (int mt = 0; mt < 5; ++mt)
                #pragma unroll
                for (int nt = 0; nt < 4; ++nt)
                    #pragma unroll
                    for (int j = 0; j < 4; ++j) acc[mt][nt][j] = 0.f;
        }
    }

    if (MODE == 0)  stats_reduce(lsum, lsq, &g_stats[0]);
    if (MODE == 12) stats_reduce(lsum, lsq, &g_stats[2]);
}

// ---------------- launcher (R14-style, 12 launches) ----------------------------
extern "C" void kernel_launch(void* const* d_in, const int* in_sizes, int n_in,
                              void* d_out, int out_size) {
    const float* x   = (const float*)d_in[0];
    const float* w1  = (const float*)d_in[1];
    const float* b1  = (const float*)d_in[2];
    const float* g1  = (const float*)d_in[3];
    const float* be1 = (const float*)d_in[4];
    const float* w21 = (const float*)d_in[5];
    const float* b21 = (const float*)d_in[6];
    const float* w22 = (const float*)d_in[7];
    const float* b22 = (const float*)d_in[8];
    const float* w23 = (const float*)d_in[9];
    const float* b23 = (const float*)d_in[10];
    const float* g2  = (const float*)d_in[11];
    const float* be2 = (const float*)d_in[12];
    const float* w3  = (const float*)d_in[13];
    const float* b3  = (const float*)d_in[14];
    float* out = (float*)d_out;

    cudaFuncSetAttribute(gemm_mma<0>,  cudaFuncAttributeMaxDynamicSharedMemorySize, SMEM_BYTES);
    cudaFuncSetAttribute(gemm_mma<10>, cudaFuncAttributeMaxDynamicSharedMemorySize, SMEM_BYTES);
    cudaFuncSetAttribute(gemm_mma<11>, cudaFuncAttributeMaxDynamicSharedMemorySize, SMEM_BYTES);
    cudaFuncSetAttribute(gemm_mma<12>, cudaFuncAttributeMaxDynamicSharedMemorySize, SMEM_BYTES);
    cudaFuncSetAttribute(gemm_mma<2>,  cudaFuncAttributeMaxDynamicSharedMemorySize, SMEM_BYTES);

    zero_stats_kernel<<<1, 32>>>();
    prep_w<<<dim3(25, 4), 256>>>(w1, w21, w22, w23);

    gemm_mma<0><<<GRID_P, NTHR, SMEM_BYTES>>>(0, x, b1, nullptr);
    finalize_kernel<<<1, CCH>>>(0, g1, be1);
    gelu_pass<<<NT / 48, 240>>>();

    gemm_mma<10><<<GRID_P, NTHR, SMEM_BYTES>>>(1, nullptr, b21, nullptr);
    gemm_mma<11><<<GRID_P, NTHR, SMEM_BYTES>>>(2, nullptr, b22, nullptr);
    gemm_mma<12><<<GRID_P, NTHR, SMEM_BYTES>>>(3, nullptr, b23, nullptr);
    finalize_kernel<<<1, CCH>>>(1, g2, be2);
    prep_w3<<<25, 256>>>(w3);
    fold_b3<<<1, CCH>>>(w3, b3);

    gemm_mma<2><<<GRID_P, NTHR, SMEM_BYTES>>>(4, nullptr, b3, out);
}

// round 16
// speedup vs baseline: 1.2205x; 1.0230x over previous
#include <cuda_runtime.h>
#include <math.h>
#include <stdint.h>
#include <stddef.h>

#define CCH 160
#define NT  110592          // 48*48*48
#define HWS 2304
#define WS  48
#define BN  192
#define NTILES (NT / BN)    // 576
#define GRID_P 148          // persistent CTAs
#define NTHR 384            // 12 warps: 2(M) x 6(N)

#define W_FLOATS  (CCH * CCH)        // 25600
#define STAGE_F   (BN * 36)          // 6912 floats per stage
#define S0        200                // mode-0 [k][n] stage stride (192 + 8)
#define NSTAGE    4
#define SMEM_FLOATS (W_FLOATS + NSTAGE * STAGE_F)   // 53248
#define SMEM_BYTES  (SMEM_FLOATS * 4)               // 212992

// ---------------- device globals (scratch; no allocation allowed) -------------
__device__ __align__(16) float g_h [(size_t)NT * CCH];   // h0 then h1 in place, [n][c]
__device__ __align__(16) float g_y [(size_t)NT * CCH];   // branch sum, [n][c]
__device__ __align__(16) float g_Wf[5 * W_FLOATS];       // fragment-ordered weights
__device__ float  g_b3f[CCH];                            // folded bias for final GEMM
__device__ double g_stats[4];
__device__ float g_alpha1[CCH], g_beta1[CCH];

// ---------------- helpers ----------------
__device__ __forceinline__ float gelu_erf(float t) {
    return 0.5f * t * (1.0f + erff(t * 0.70710678118654752f));
}
__device__ __forceinline__ float rna_tf32(float x) {
    float r; asm("cvt.rna.tf32.f32 %0, %1;" : "=f"(r) : "f"(x)); return r;
}
__device__ __forceinline__ void mma8(float* c, uint4 a, uint32_t b0, uint32_t b1) {
    asm("mma.sync.aligned.m16n8k8.row.col.f32.tf32.tf32.f32 "
        "{%0,%1,%2,%3}, {%4,%5,%6,%7}, {%8,%9}, {%0,%1,%2,%3};"
        : "+f"(c[0]), "+f"(c[1]), "+f"(c[2]), "+f"(c[3])
        : "r"(a.x), "r"(a.y), "r"(a.z), "r"(a.w), "r"(b0), "r"(b1));
}
__device__ __forceinline__ uint32_t smem_u32(const void* p) {
    uint32_t a;
    asm("{ .reg .u64 t; cvta.to.shared.u64 t, %1; cvt.u32.u64 %0, t; }" : "=r"(a) : "l"(p));
    return a;
}
__device__ __forceinline__ void cpa16(uint32_t dst, const void* src, int sz) {
    asm volatile("cp.async.ca.shared.global [%0], [%1], 16, %2;"
                 :: "r"(dst), "l"(src), "r"(sz) : "memory");
}
#define CPA_COMMIT() asm volatile("cp.async.commit_group;" ::: "memory")
#define CPA_WAIT2()  asm volatile("cp.async.wait_group 2;" ::: "memory")

// ---------------- prep: fragment-order + tf32-round weights; zero stats ------
__global__ void prep_w(const float* __restrict__ w1, const float* __restrict__ w21,
                       const float* __restrict__ w22, const float* __restrict__ w23) {
    if (blockIdx.x == 0 && blockIdx.y == 0 && threadIdx.x < 4)
        g_stats[threadIdx.x] = 0.0;
    const int gid = blockIdx.y;
    const float* W = (gid == 0) ? w1 : (gid == 1) ? w21 : (gid == 2) ? w22 : w23;
    int idx = blockIdx.x * 256 + threadIdx.x;       // < 6400
    if (idx >= 6400) return;
    int mtile = idx / 640;
    int rem   = idx % 640;
    int kstep = rem / 32;
    int lane  = rem % 32;
    int g = lane >> 2, tig = lane & 3;
    int m0 = mtile * 16 + g;
    int k0 = kstep * 8 + tig;
    float4 o;
    o.x = rna_tf32(W[m0 * CCH + k0]);
    o.y = rna_tf32(W[(m0 + 8) * CCH + k0]);
    o.z = rna_tf32(W[m0 * CCH + k0 + 4]);
    o.w = rna_tf32(W[(m0 + 8) * CCH + k0 + 4]);
    reinterpret_cast<float4*>(g_Wf)[(size_t)gid * 6400 + idx] = o;
}

// ---------------- GN1 finalize (stage 0 only) ---------------------------------
__global__ void finalize_kernel(const float* __restrict__ g,
                                const float* __restrict__ be) {
    __shared__ double sh[2];
    if (threadIdx.x == 0) {
        double Nd = (double)CCH * (double)NT;
        double m  = g_stats[0] / Nd;
        double v  = g_stats[1] / Nd - m * m;
        sh[0] = m; sh[1] = 1.0 / sqrt(v + 1e-5);
    }
    __syncthreads();
    const int c = threadIdx.x;
    double mu = sh[0], rs = sh[1];
    g_alpha1[c] = (float)((double)g[c] * rs);
    g_beta1[c]  = (float)((double)be[c] - mu * (double)g[c] * rs);
}

// ---------------- GN2 finalize + w3/b3 fold, one kernel ------------------------
// blocks 0..24: fragment-order w3*alpha2 into gid slot 4; block 25: b3' = b3 + w3@beta2
__global__ void final_prep(const float* __restrict__ w3, const float* __restrict__ b3,
                           const float* __restrict__ g2, const float* __restrict__ be2) {
    __shared__ double sMu, sRs;
    __shared__ float sA[CCH], sB[CCH];
    const int t = threadIdx.x;
    if (t == 0) {
        double Nd = (double)CCH * (double)NT;
        double m  = g_stats[2] / Nd;
        double v  = g_stats[3] / Nd - m * m;
        sMu = m; sRs = 1.0 / sqrt(v + 1e-5);
    }
    __syncthreads();
    if (t < CCH) {
        double mu = sMu, rs = sRs;
        sA[t] = (float)((double)g2[t] * rs);
        sB[t] = (float)((double)be2[t] - mu * (double)g2[t] * rs);
    }
    __syncthreads();
    if (blockIdx.x < 25) {
        int idx = blockIdx.x * 256 + t;             // < 6400
        int mtile = idx / 640;
        int rem   = idx % 640;
        int kstep = rem / 32;
        int lane  = rem % 32;
        int g = lane >> 2, tig = lane & 3;
        int m0 = mtile * 16 + g;
        int k0 = kstep * 8 + tig;
        float4 o;
        o.x = rna_tf32(w3[m0 * CCH + k0]       * sA[k0]);
        o.y = rna_tf32(w3[(m0 + 8) * CCH + k0] * sA[k0]);
        o.z = rna_tf32(w3[m0 * CCH + k0 + 4]       * sA[k0 + 4]);
        o.w = rna_tf32(w3[(m0 + 8) * CCH + k0 + 4] * sA[k0 + 4]);
        reinterpret_cast<float4*>(g_Wf)[(size_t)4 * 6400 + idx] = o;
    } else if (t < CCH) {
        float s = b3[t];
        for (int k = 0; k < CCH; ++k) s += w3[t * CCH + k] * sB[k];
        g_b3f[t] = s;
    }
}

// h1 = rna(gelu(affine1(h0))) in place, [n][c].
// Index-math-free inner loop: 240 thr; thread owns fixed channel c0=(t%40)*4.
__global__ void __launch_bounds__(240) gelu_pass() {
    const int t = threadIdx.x;
    const int r_off = t / 40;          // 0..5
    const int c0    = (t % 40) * 4;
    const float4 al = *reinterpret_cast<const float4*>(&g_alpha1[c0]);
    const float4 bt = *reinterpret_cast<const float4*>(&g_beta1[c0]);
    const int rbase = blockIdx.x * 48 + r_off;
    #pragma unroll
    for (int i = 0; i < 8; ++i) {
        const size_t r = (size_t)(rbase + i * 6);
        float4* p = reinterpret_cast<float4*>(g_h + r * CCH + c0);
        float4 v = *p;
        v.x = rna_tf32(gelu_erf(fmaf(al.x, v.x, bt.x)));
        v.y = rna_tf32(gelu_erf(fmaf(al.y, v.y, bt.y)));
        v.z = rna_tf32(gelu_erf(fmaf(al.z, v.z, bt.z)));
        v.w = rna_tf32(gelu_erf(fmaf(al.w, v.w, bt.w)));
        *p = v;
    }
}

__device__ __forceinline__ void stats_reduce(float lsum, float lsq, double* dst) {
    double s = (double)lsum, q = (double)lsq;
    #pragma unroll
    for (int o = 16; o > 0; o >>= 1) {
        s += __shfl_down_sync(0xffffffffu, s, o);
        q += __shfl_down_sync(0xffffffffu, q, o);
    }
    __shared__ double red[32];
    const int w = threadIdx.x >> 5, l = threadIdx.x & 31;
    if (l == 0) { red[w] = s; red[16 + w] = q; }
    __syncthreads();
    if (threadIdx.x == 0) {
        double S = 0.0, Q = 0.0;
        #pragma unroll
        for (int i = 0; i < 12; ++i) { S += red[i]; Q += red[16 + i]; }
        atomicAdd(&dst[0], S);
        atomicAdd(&dst[1], Q);
    }
}

// ---------------- persistent multistage tf32 mma GEMM (R15 core, fills hoisted)
// MODE 0 : h0 = W1@x  + b1   (B = x direct, [k][n] stage)  -> g_h, GN1 stats
// MODE 10: y  = gelu(W21@sh_d(h1) + b21)    -> g_y store
// MODE 11: y += gelu(W22@sh_h(h1) + b22)    -> g_y RMW
// MODE 12: y += gelu(W23@sh_w(h1) + b23)    -> g_y RMW (rna), GN2 stats
// MODE 2 : out = W3'@y + b3'                -> Outp [c][n]
template<int MODE>
__global__ void __launch_bounds__(NTHR, 1) gemm_mma(
    int gid, const float* __restrict__ Xp,
    const float* __restrict__ bias, float* __restrict__ Outp)
{
    extern __shared__ __align__(16) float smem[];
    float* Ws = smem;
    const uint32_t ws_u = smem_u32(smem);
    const uint32_t bs_u = ws_u + W_FLOATS * 4;

    const int t = threadIdx.x;
    const int lane = t & 31, wid = t >> 5;
    const int warp_m = wid & 1, warp_n = wid >> 1;   // 2 x 6, warp covers 32 cols
    const int g = lane >> 2, tig = lane & 3;
    const int bid = blockIdx.x;

    // W fill (async, first group)
    {
        const float* wsrc = g_Wf + (size_t)gid * W_FLOATS;
        #pragma unroll
        for (int i = 0; i < 17; ++i) {
            const int e = t + i * NTHR;
            if (e < 6400)
                cpa16(ws_u + (uint32_t)e * 16, wsrc + (size_t)e * 4, 16);
        }
        CPA_COMMIT();
    }

    const int ntile = (NTILES - bid + GRID_P - 1) / GRID_P;
    const int nq = ntile * 5;
    const float* Bsrc = (MODE == 0) ? Xp : ((MODE == 2) ? g_y : g_h);

    const int r0 = t >> 3;        // [n][c] fill: rows r0 + i*48  (i<4)
    const int fj = t & 7;         // 16B chunk within 32-ch row

    // mode-0 fill: hoisted per-thread (k, c4) decomposition
    int m0k0 = 0, m0k1 = 0, m0k2 = 0, m0k3 = 0;       // row within 32-k chunk
    int m0c0 = 0, m0c1 = 0, m0c2 = 0, m0c3 = 0;       // float4 col
    if (MODE == 0) {
        m0k0 = t / 48;            m0c0 = t % 48;
        m0k1 = (t + 384) / 48;    m0c1 = (t + 384) % 48;
        m0k2 = (t + 768) / 48;    m0c2 = (t + 768) % 48;
        m0k3 = (t + 1152) / 48;   m0c3 = (t + 1152) % 48;
    }

    // shift modes: per-tile hoisted state (recomputed at kc==0; fill q strictly increases)
    const int stride = (MODE == 10) ? HWS : ((MODE == 11) ? WS : 1);
    const ptrdiff_t kdelta = (ptrdiff_t)32 - (ptrdiff_t)stride * CCH;  // src step per kc
    const float* sb0; const float* sb1; const float* sb2; const float* sb3;
    int si0, si1, si2, si3;

    auto fill = [&](int q) {
        if (q >= nq) return;
        const int tl = q / 5, kc = q % 5;
        const int tileN = (bid + tl * GRID_P) * BN;
        const uint32_t dbase = bs_u + (uint32_t)(q & 3) * (STAGE_F * 4);
        if (MODE == 0) {
            const float* base = Bsrc + (size_t)(kc * 32) * NT + tileN;
            cpa16(dbase + (uint32_t)(m0k0 * S0 + m0c0 * 4) * 4, base + (size_t)m0k0 * NT + m0c0 * 4, 16);
            cpa16(dbase + (uint32_t)(m0k1 * S0 + m0c1 * 4) * 4, base + (size_t)m0k1 * NT + m0c1 * 4, 16);
            cpa16(dbase + (uint32_t)(m0k2 * S0 + m0c2 * 4) * 4, base + (size_t)m0k2 * NT + m0c2 * 4, 16);
            cpa16(dbase + (uint32_t)(m0k3 * S0 + m0c3 * 4) * 4, base + (size_t)m0k3 * NT + m0c3 * 4, 16);
        } else if (MODE == 2) {
            #pragma unroll
            for (int i = 0; i < 4; ++i) {
                const int r = r0 + i * 48;
                cpa16(dbase + (uint32_t)(r * 36 + fj * 4) * 4,
                      Bsrc + (size_t)(tileN + r) * CCH + kc * 32 + fj * 4, 16);
            }
        } else {
            if (kc == 0) {   // hoist: recompute per-tile bases once per 5 chunks
                #pragma unroll
                for (int i = 0; i < 4; ++i) {
                    const int n = tileN + r0 + i * 48;
                    const int idx = (MODE == 10) ? (n / HWS)
                                  : (MODE == 11) ? ((n / WS) % WS) : (n % WS);
                    const float* sb = Bsrc + (size_t)(n + 2 * stride) * CCH + fj * 4;
                    if (i == 0) { sb0 = sb; si0 = idx; }
                    if (i == 1) { sb1 = sb; si1 = idx; }
                    if (i == 2) { sb2 = sb; si2 = idx; }
                    if (i == 3) { sb3 = sb; si3 = idx; }
                }
            }
            const ptrdiff_t koff = (ptrdiff_t)kc * kdelta;
            #pragma unroll
            for (int i = 0; i < 4; ++i) {
                const int r = r0 + i * 48;
                const float* sb = (i == 0) ? sb0 : (i == 1) ? sb1 : (i == 2) ? sb2 : sb3;
                const int si    = (i == 0) ? si0 : (i == 1) ? si1 : (i == 2) ? si2 : si3;
                const int sz = ((unsigned)(si + 2 - kc) < (unsigned)WS) ? 16 : 0;
                cpa16(dbase + (uint32_t)(r * 36 + fj * 4) * 4, sb + koff, sz);
            }
        }
    };

    fill(0); CPA_COMMIT();
    fill(1); CPA_COMMIT();
    fill(2); CPA_COMMIT();

    float acc[5][4][4];
    #pragma unroll
    for (int mt = 0; mt < 5; ++mt)
        #pragma unroll
        for (int nt = 0; nt < 4; ++nt)
            #pragma unroll
            for (int j = 0; j < 4; ++j) acc[mt][nt][j] = 0.f;
    float lsum = 0.f, lsq = 0.f;

    #pragma unroll 1
    for (int q = 0; q < nq; ++q) {
        CPA_WAIT2();
        __syncthreads();
        // safe: stage (q+3)&3 == (q-1)&3 was last read in iter q-1; sync above fences it
        fill(q + 3);
        CPA_COMMIT();

        const int kc = q % 5;
        const float* Bb = smem + W_FLOATS + (q & 3) * STAGE_F;

        #pragma unroll
        for (int ksl = 0; ksl < 4; ++ksl) {
            const int ks = kc * 4 + ksl;
            uint4 af[5];
            #pragma unroll
            for (int mt = 0; mt < 5; ++mt)
                af[mt] = *reinterpret_cast<const uint4*>(
                    &Ws[(((warp_m * 5 + mt) * 20 + ks) * 32 + lane) * 4]);
            #pragma unroll
            for (int nt = 0; nt < 4; ++nt) {
                const int nn = warp_n * 32 + nt * 8 + g;
                uint32_t b0, b1;
                if (MODE == 0) {
                    b0 = __float_as_uint(Bb[(ksl * 8 + tig) * S0 + nn]);
                    b1 = __float_as_uint(Bb[(ksl * 8 + tig + 4) * S0 + nn]);
                } else {
                    b0 = __float_as_uint(Bb[nn * 36 + ksl * 8 + tig]);
                    b1 = __float_as_uint(Bb[nn * 36 + ksl * 8 + tig + 4]);
                }
                #pragma unroll
                for (int mt = 0; mt < 5; ++mt)
                    mma8(acc[mt][nt], af[mt], b0, b1);
            }
        }

        if (kc == 4) {
            // ---- tile epilogue ----
            const int tileN = (bid + (q / 5) * GRID_P) * BN;
            if (MODE != 2) {
                #pragma unroll
                for (int mt = 0; mt < 5; ++mt) {
                    const int m0 = warp_m * 80 + mt * 16 + g;
                    const float bb0 = bias[m0], bb1 = bias[m0 + 8];
                    #pragma unroll
                    for (int nt = 0; nt < 4; ++nt) {
                        const int n0 = tileN + warp_n * 32 + nt * 8 + tig * 2;
                        float v[4];
                        v[0] = acc[mt][nt][0] + bb0;
                        v[1] = acc[mt][nt][1] + bb0;
                        v[2] = acc[mt][nt][2] + bb1;
                        v[3] = acc[mt][nt][3] + bb1;
                        const size_t a00 = (size_t)n0 * CCH + m0;
                        const size_t a01 = (size_t)(n0 + 1) * CCH + m0;
                        if (MODE == 0) {
                            #pragma unroll
                            for (int j = 0; j < 4; ++j) { lsum += v[j]; lsq += v[j] * v[j]; }
                            g_h[a00] = v[0]; g_h[a01] = v[1];
                            g_h[a00 + 8] = v[2]; g_h[a01 + 8] = v[3];
                        } else {
                            #pragma unroll
                            for (int j = 0; j < 4; ++j) v[j] = gelu_erf(v[j]);
                            if (MODE != 10) {
                                v[0] += g_y[a00]; v[1] += g_y[a01];
                                v[2] += g_y[a00 + 8]; v[3] += g_y[a01 + 8];
                            }
                            if (MODE == 12) {
                                #pragma unroll
                                for (int j = 0; j < 4; ++j) {
                                    lsum += v[j]; lsq += v[j] * v[j];
                                    v[j] = rna_tf32(v[j]);     // final y, pre-rounded for GEMM 2
                                }
                            }
                            g_y[a00] = v[0]; g_y[a01] = v[1];
                            g_y[a00 + 8] = v[2]; g_y[a01 + 8] = v[3];
                        }
                    }
                }
            } else {
                #pragma unroll
                for (int mt = 0; mt < 5; ++mt) {
                    const int m0 = warp_m * 80 + mt * 16 + g;
                    const float bb0 = g_b3f[m0], bb1 = g_b3f[m0 + 8];
                    #pragma unroll
                    for (int nt = 0; nt < 4; ++nt) {
                        const int n0 = tileN + warp_n * 32 + nt * 8 + tig * 2;
                        float2 o0 = {acc[mt][nt][0] + bb0, acc[mt][nt][1] + bb0};
                        float2 o1 = {acc[mt][nt][2] + bb1, acc[mt][nt][3] + bb1};
                        *reinterpret_cast<float2*>(Outp + (size_t)m0 * NT + n0)       = o0;
                        *reinterpret_cast<float2*>(Outp + (size_t)(m0 + 8) * NT + n0) = o1;
                    }
                }
            }
            #pragma unroll
            for (int mt = 0; mt < 5; ++mt)
                #pragma unroll
                for (int nt = 0; nt < 4; ++nt)
                    #pragma unroll
                    for (int j = 0; j < 4; ++j) acc[mt][nt][j] = 0.f;
        }
    }

    if (MODE == 0)  stats_reduce(lsum, lsq, &g_stats[0]);
    if (MODE == 12) stats_reduce(lsum, lsq, &g_stats[2]);
}

// ---------------- launcher ----------------------------------------------------
extern "C" void kernel_launch(void* const* d_in, const int* in_sizes, int n_in,
                              void* d_out, int out_size) {
    const float* x   = (const float*)d_in[0];
    const float* w1  = (const float*)d_in[1];
    const float* b1  = (const float*)d_in[2];
    const float* g1  = (const float*)d_in[3];
    const float* be1 = (const float*)d_in[4];
    const float* w21 = (const float*)d_in[5];
    const float* b21 = (const float*)d_in[6];
    const float* w22 = (const float*)d_in[7];
    const float* b22 = (const float*)d_in[8];
    const float* w23 = (const float*)d_in[9];
    const float* b23 = (const float*)d_in[10];
    const float* g2  = (const float*)d_in[11];
    const float* be2 = (const float*)d_in[12];
    const float* w3  = (const float*)d_in[13];
    const float* b3  = (const float*)d_in[14];
    float* out = (float*)d_out;

    cudaFuncSetAttribute(gemm_mma<0>,  cudaFuncAttributeMaxDynamicSharedMemorySize, SMEM_BYTES);
    cudaFuncSetAttribute(gemm_mma<10>, cudaFuncAttributeMaxDynamicSharedMemorySize, SMEM_BYTES);
    cudaFuncSetAttribute(gemm_mma<11>, cudaFuncAttributeMaxDynamicSharedMemorySize, SMEM_BYTES);
    cudaFuncSetAttribute(gemm_mma<12>, cudaFuncAttributeMaxDynamicSharedMemorySize, SMEM_BYTES);
    cudaFuncSetAttribute(gemm_mma<2>,  cudaFuncAttributeMaxDynamicSharedMemorySize, SMEM_BYTES);

    prep_w<<<dim3(25, 4), 256>>>(w1, w21, w22, w23);

    gemm_mma<0><<<GRID_P, NTHR, SMEM_BYTES>>>(0, x, b1, nullptr);
    finalize_kernel<<<1, CCH>>>(g1, be1);
    gelu_pass<<<NT / 48, 240>>>();

    gemm_mma<10><<<GRID_P, NTHR, SMEM_BYTES>>>(1, nullptr, b21, nullptr);
    gemm_mma<11><<<GRID_P, NTHR, SMEM_BYTES>>>(2, nullptr, b22, nullptr);
    gemm_mma<12><<<GRID_P, NTHR, SMEM_BYTES>>>(3, nullptr, b23, nullptr);
    final_prep<<<26, 256>>>(w3, b3, g2, be2);

    gemm_mma<2><<<GRID_P, NTHR, SMEM_BYTES>>>(4, nullptr, b3, out);
}